// round 10
// baseline (speedup 1.0000x reference)
#include <cuda_runtime.h>
#include <cuda_bf16.h>
#include <cuda_fp16.h>
#include <math.h>
#include <stdint.h>

#define NN    50000
#define EE    800000
#define ETOT  (EE + NN)
#define NEG_SLOPE 0.2f
#define BN_EPS    1e-5f

// ---------------- scratch (device globals; no allocation) ----------------
__device__ float  g_hp[(size_t)NN * 40];       // layer-3 h (fp32)
__device__ __half g_hph[(size_t)NN * 128];     // layers 1/2 h (fp16, agg input)
__device__ __half g_fhi[(size_t)NN * 128];     // feat hi/lo (fp16 split, GEMM input)
__device__ __half g_flo[(size_t)NN * 128];
__device__ float g_al_src[NN * 4];
__device__ float g_al_dst[NN * 4];
__device__ int   g_deg[NN];
__device__ int   g_rank[ETOT];
__device__ int   g_incl[NN + 1024];
__device__ int   g_bsum[64];
__device__ int   g_rowptr[NN + 1];
__device__ int   g_csrsrc[ETOT];

__device__ __forceinline__ uint32_t smem_u32(const void* p) {
    uint32_t a;
    asm("{ .reg .u64 t; cvta.to.shared.u64 t, %1; cvt.u32.u64 %0, t; }" : "=r"(a) : "l"(p));
    return a;
}

// =========================== CSR build ===========================
// hist also records each edge's arrival rank within its dst bucket
__global__ void hist_kernel(const int* __restrict__ ei, int E0, int n,
                            int* __restrict__ deg, int* __restrict__ rank)
{
    int t = blockIdx.x * blockDim.x + threadIdx.x;
    if (t >= E0 + n) return;
    int d = (t < E0) ? ei[E0 + t] : (t - E0);
    rank[t] = atomicAdd(&deg[d], 1);
}

__global__ void scan1_kernel(const int* __restrict__ deg, int* __restrict__ incl,
                             int* __restrict__ bsum, int n)
{
    __shared__ int sh[1024];
    int i = blockIdx.x * 1024 + threadIdx.x;
    int v = (i < n) ? deg[i] : 0;
    sh[threadIdx.x] = v;
    __syncthreads();
#pragma unroll
    for (int o = 1; o < 1024; o <<= 1) {
        int t = (threadIdx.x >= o) ? sh[threadIdx.x - o] : 0;
        __syncthreads();
        sh[threadIdx.x] += t;
        __syncthreads();
    }
    incl[i] = sh[threadIdx.x];
    if (threadIdx.x == 1023) bsum[blockIdx.x] = sh[1023];
}

__global__ void scan3_kernel(const int* __restrict__ incl, const int* __restrict__ bsum,
                             int* __restrict__ rowptr, int n, int nb)
{
    __shared__ int pref[64];
    if (threadIdx.x == 0) {
        int acc = 0;
        for (int b = 0; b < nb; b++) { pref[b] = acc; acc += bsum[b]; }
    }
    __syncthreads();
    int i = blockIdx.x * blockDim.x + threadIdx.x;
    if (i < n) rowptr[i + 1] = incl[i] + pref[i >> 10];
    if (i == 0) rowptr[0] = 0;
}

// atomic-free scatter: position = rowptr[dst] + recorded rank
__global__ void scatter_kernel(const int* __restrict__ ei, int E0, int n,
                               const int* __restrict__ rowptr,
                               const int* __restrict__ rank,
                               int* __restrict__ csrsrc)
{
    int t = blockIdx.x * blockDim.x + threadIdx.x;
    if (t >= E0 + n) return;
    int s, d;
    if (t < E0) { s = ei[t]; d = ei[E0 + t]; }
    else        { s = d = t - E0; }
    csrsrc[rowptr[d] + rank[t]] = s;
}

// =========================== HMMA common (fp16, 2-pass split) ===========================
#define SROW    272
#define SM_AHI  0
#define SM_ALO  34816
#define SM_B    69632
#define SM_TOT  104448

#define SROWB   144
#define SM4_B   69632
#define SM4_SAL 88064
#define SM4_TOT 89088

__device__ __forceinline__ void ldsm_x4(uint32_t& r0, uint32_t& r1, uint32_t& r2,
                                        uint32_t& r3, uint32_t addr) {
    asm volatile("ldmatrix.sync.aligned.m8n8.x4.shared.b16 {%0,%1,%2,%3}, [%4];"
                 : "=r"(r0), "=r"(r1), "=r"(r2), "=r"(r3) : "r"(addr));
}
__device__ __forceinline__ void ldsm_x4_t(uint32_t& r0, uint32_t& r1, uint32_t& r2,
                                          uint32_t& r3, uint32_t addr) {
    asm volatile("ldmatrix.sync.aligned.m8n8.x4.trans.shared.b16 {%0,%1,%2,%3}, [%4];"
                 : "=r"(r0), "=r"(r1), "=r"(r2), "=r"(r3) : "r"(addr));
}
__device__ __forceinline__ void mma_f16(float* c, uint32_t a0, uint32_t a1, uint32_t a2,
                                        uint32_t a3, uint32_t b0, uint32_t b1) {
    asm volatile("mma.sync.aligned.m16n8k16.row.col.f32.f16.f16.f32 "
                 "{%0,%1,%2,%3}, {%4,%5,%6,%7}, {%8,%9}, {%0,%1,%2,%3};"
                 : "+f"(c[0]), "+f"(c[1]), "+f"(c[2]), "+f"(c[3])
                 : "r"(a0), "r"(a1), "r"(a2), "r"(a3), "r"(b0), "r"(b1));
}

__device__ __forceinline__ void split8h(const float* f, uint4* hi, uint4* lo) {
    __half h8[8], l8[8];
#pragma unroll
    for (int q = 0; q < 8; q++) {
        h8[q] = __float2half_rn(f[q]);
        l8[q] = __float2half_rn(f[q] - __half2float(h8[q]));
    }
    *hi = *(uint4*)h8;
    *lo = *(uint4*)l8;
}

// ===== wide GEMM 128x128 (A fp16 hi/lo, B fp16) + fused al dots; D fp16 =====
template<bool A32>
__global__ __launch_bounds__(256, 2) void mma_gemm128_kernel(
    const float* __restrict__ Af,
    const __half* __restrict__ Ahi, const __half* __restrict__ Alo,
    const float* __restrict__ W,
    const float* __restrict__ asrc, const float* __restrict__ adst,
    __half* __restrict__ hph, float* __restrict__ als, float* __restrict__ ald, int n)
{
    extern __shared__ char smem[];
    int tid = threadIdx.x, wid = tid >> 5, lane = tid & 31;
    int r0 = blockIdx.x * 128;

    for (int i = tid; i < 2048; i += 256) {
        int row = i >> 4, ch = i & 15;
        uint4 vh, vl;
        if (A32) {
            float f[8];
            if (r0 + row < n) {
                *(float4*)(f)     = *(const float4*)(Af + (size_t)(r0 + row) * 128 + ch * 8);
                *(float4*)(f + 4) = *(const float4*)(Af + (size_t)(r0 + row) * 128 + ch * 8 + 4);
            } else {
#pragma unroll
                for (int q = 0; q < 8; q++) f[q] = 0.f;
            }
            split8h(f, &vh, &vl);
        } else {
            if (r0 + row < n) {
                vh = *(const uint4*)(Ahi + (size_t)(r0 + row) * 128 + ch * 8);
                vl = *(const uint4*)(Alo + (size_t)(r0 + row) * 128 + ch * 8);
            } else {
                vh = make_uint4(0u, 0u, 0u, 0u); vl = vh;
            }
        }
        *(uint4*)(smem + SM_AHI + row * SROW + ch * 16) = vh;
        *(uint4*)(smem + SM_ALO + row * SROW + ch * 16) = vl;
    }
    for (int i = tid; i < 2048; i += 256) {
        int row = i >> 4, ch = i & 15;
        float f[8];
        *(float4*)(f)     = *(const float4*)(W + (size_t)row * 128 + ch * 8);
        *(float4*)(f + 4) = *(const float4*)(W + (size_t)row * 128 + ch * 8 + 4);
        __half h8[8];
#pragma unroll
        for (int q = 0; q < 8; q++) h8[q] = __float2half_rn(f[q]);
        *(uint4*)(smem + SM_B + row * SROW + ch * 16) = *(uint4*)h8;
    }
    __syncthreads();

    int wm = wid & 3;
    int wn = wid >> 2;
    uint32_t sb = smem_u32(smem);

    float c[2][8][4];
#pragma unroll
    for (int mt = 0; mt < 2; mt++)
#pragma unroll
        for (int nt = 0; nt < 8; nt++)
#pragma unroll
            for (int q = 0; q < 4; q++) c[mt][nt][q] = 0.f;

    int q  = lane >> 3;
    int lr = lane & 7;
    int a_row_in = wm * 32 + lr + (q & 1) * 8;
    int a_koff   = (q >> 1) * 8;
    int b_krow   = lr + (q & 1) * 8;
    int b_ncol0  = wn * 64 + (q >> 1) * 8;

    uint32_t bbase = sb + SM_B;
#pragma unroll
    for (int s = 0; s < 2; s++) {
        uint32_t abase = sb + ((s == 1) ? SM_ALO : SM_AHI);
#pragma unroll
        for (int ks = 0; ks < 8; ks++) {
            int k0 = ks * 16;
            uint32_t a0[4], a1[4];
            ldsm_x4(a0[0], a0[1], a0[2], a0[3],
                    abase + (a_row_in) * SROW + (k0 + a_koff) * 2);
            ldsm_x4(a1[0], a1[1], a1[2], a1[3],
                    abase + (a_row_in + 16) * SROW + (k0 + a_koff) * 2);
#pragma unroll
            for (int nt = 0; nt < 4; nt++) {
                uint32_t b[4];
                ldsm_x4_t(b[0], b[1], b[2], b[3],
                          bbase + (k0 + b_krow) * SROW + (b_ncol0 + nt * 16) * 2);
                mma_f16(c[0][nt * 2 + 0], a0[0], a0[1], a0[2], a0[3], b[0], b[1]);
                mma_f16(c[0][nt * 2 + 1], a0[0], a0[1], a0[2], a0[3], b[2], b[3]);
                mma_f16(c[1][nt * 2 + 0], a1[0], a1[1], a1[2], a1[3], b[0], b[1]);
                mma_f16(c[1][nt * 2 + 1], a1[0], a1[1], a1[2], a1[3], b[2], b[3]);
            }
        }
    }

    int trow = lane >> 2, tcol = (lane & 3) * 2;

#pragma unroll
    for (int mt = 0; mt < 2; mt++) {
        int rbase = r0 + wm * 32 + mt * 16 + trow;
#pragma unroll
        for (int nt = 0; nt < 8; nt++) {
            int col = wn * 64 + nt * 8 + tcol;
            if (rbase < n)
                *(__half2*)(hph + (size_t)rbase * 128 + col) =
                    __floats2half2_rn(c[mt][nt][0], c[mt][nt][1]);
            if (rbase + 8 < n)
                *(__half2*)(hph + (size_t)(rbase + 8) * 128 + col) =
                    __floats2half2_rn(c[mt][nt][2], c[mt][nt][3]);
        }
    }

    float ap[2][4], dp[2][4];
#pragma unroll
    for (int hh = 0; hh < 2; hh++)
#pragma unroll
        for (int v = 0; v < 4; v++) { ap[hh][v] = 0.f; dp[hh][v] = 0.f; }
#pragma unroll
    for (int nt = 0; nt < 8; nt++) {
        int col = wn * 64 + nt * 8 + tcol;
        int hh = nt >> 2;
        float s0 = __ldg(asrc + col), s1 = __ldg(asrc + col + 1);
        float d0 = __ldg(adst + col), d1 = __ldg(adst + col + 1);
#pragma unroll
        for (int mt = 0; mt < 2; mt++) {
            ap[hh][mt * 2 + 0] += c[mt][nt][0] * s0 + c[mt][nt][1] * s1;
            ap[hh][mt * 2 + 1] += c[mt][nt][2] * s0 + c[mt][nt][3] * s1;
            dp[hh][mt * 2 + 0] += c[mt][nt][0] * d0 + c[mt][nt][1] * d1;
            dp[hh][mt * 2 + 1] += c[mt][nt][2] * d0 + c[mt][nt][3] * d1;
        }
    }
#pragma unroll
    for (int off = 1; off <= 2; off <<= 1)
#pragma unroll
        for (int hh = 0; hh < 2; hh++)
#pragma unroll
            for (int v = 0; v < 4; v++) {
                ap[hh][v] += __shfl_xor_sync(0xffffffffu, ap[hh][v], off);
                dp[hh][v] += __shfl_xor_sync(0xffffffffu, dp[hh][v], off);
            }
    if ((lane & 3) == 0) {
#pragma unroll
        for (int mt = 0; mt < 2; mt++)
#pragma unroll
            for (int rr = 0; rr < 2; rr++) {
                int row = r0 + wm * 32 + mt * 16 + trow + rr * 8;
                int v = mt * 2 + rr;
                if (row < n) {
                    als[row * 4 + wn * 2 + 0] = ap[0][v];
                    als[row * 4 + wn * 2 + 1] = ap[1][v];
                    ald[row * 4 + wn * 2 + 0] = dp[0][v];
                    ald[row * 4 + wn * 2 + 1] = dp[1][v];
                }
            }
    }
}

// ===== layer-3 GEMM: [n,128] @ [128,40] (A fp16 hi/lo, B fp16, N padded 64) =====
__global__ __launch_bounds__(256, 2) void mma_gemm40_kernel(
    const __half* __restrict__ Ahi, const __half* __restrict__ Alo,
    const float* __restrict__ W,
    const float* __restrict__ asrc, const float* __restrict__ adst,
    float* __restrict__ C, float* __restrict__ als, float* __restrict__ ald, int n)
{
    extern __shared__ char smem[];
    float* salS = (float*)(smem + SM4_SAL);
    float* salD = salS + 128;
    int tid = threadIdx.x, wid = tid >> 5, lane = tid & 31;
    int r0 = blockIdx.x * 128;

    for (int i = tid; i < 2048; i += 256) {
        int row = i >> 4, ch = i & 15;
        uint4 vh, vl;
        if (r0 + row < n) {
            vh = *(const uint4*)(Ahi + (size_t)(r0 + row) * 128 + ch * 8);
            vl = *(const uint4*)(Alo + (size_t)(r0 + row) * 128 + ch * 8);
        } else {
            vh = make_uint4(0u, 0u, 0u, 0u); vl = vh;
        }
        *(uint4*)(smem + SM_AHI + row * SROW + ch * 16) = vh;
        *(uint4*)(smem + SM_ALO + row * SROW + ch * 16) = vl;
    }
    for (int i = tid; i < 8192; i += 256) {
        int row = i >> 6, cc = i & 63;
        float f = (cc < 40) ? W[(size_t)row * 40 + cc] : 0.f;
        *(__half*)(smem + SM4_B + row * SROWB + cc * 2) = __float2half_rn(f);
    }
    if (tid < 128) { salS[tid] = 0.f; salD[tid] = 0.f; }
    __syncthreads();

    int wm = wid & 3;
    int wn = wid >> 2;
    uint32_t sb = smem_u32(smem);

    float c[2][4][4];
#pragma unroll
    for (int mt = 0; mt < 2; mt++)
#pragma unroll
        for (int nt = 0; nt < 4; nt++)
#pragma unroll
            for (int q = 0; q < 4; q++) c[mt][nt][q] = 0.f;

    int q  = lane >> 3;
    int lr = lane & 7;
    int a_row_in = wm * 32 + lr + (q & 1) * 8;
    int a_koff   = (q >> 1) * 8;
    int b_krow   = lr + (q & 1) * 8;
    int b_ncol0  = wn * 32 + (q >> 1) * 8;

    uint32_t bbase = sb + SM4_B;
#pragma unroll
    for (int s = 0; s < 2; s++) {
        uint32_t abase = sb + ((s == 1) ? SM_ALO : SM_AHI);
#pragma unroll
        for (int ks = 0; ks < 8; ks++) {
            int k0 = ks * 16;
            uint32_t a0[4], a1[4];
            ldsm_x4(a0[0], a0[1], a0[2], a0[3],
                    abase + (a_row_in) * SROW + (k0 + a_koff) * 2);
            ldsm_x4(a1[0], a1[1], a1[2], a1[3],
                    abase + (a_row_in + 16) * SROW + (k0 + a_koff) * 2);
#pragma unroll
            for (int nt = 0; nt < 2; nt++) {
                uint32_t b[4];
                ldsm_x4_t(b[0], b[1], b[2], b[3],
                          bbase + (k0 + b_krow) * SROWB + (b_ncol0 + nt * 16) * 2);
                mma_f16(c[0][nt * 2 + 0], a0[0], a0[1], a0[2], a0[3], b[0], b[1]);
                mma_f16(c[0][nt * 2 + 1], a0[0], a0[1], a0[2], a0[3], b[2], b[3]);
                mma_f16(c[1][nt * 2 + 0], a1[0], a1[1], a1[2], a1[3], b[0], b[1]);
                mma_f16(c[1][nt * 2 + 1], a1[0], a1[1], a1[2], a1[3], b[2], b[3]);
            }
        }
    }

    int trow = lane >> 2, tcol = (lane & 3) * 2;

#pragma unroll
    for (int mt = 0; mt < 2; mt++) {
        int rbase = r0 + wm * 32 + mt * 16 + trow;
#pragma unroll
        for (int nt = 0; nt < 4; nt++) {
            int col = wn * 32 + nt * 8 + tcol;
            if (col < 40) {
                if (rbase < n)
                    *(float2*)(C + (size_t)rbase * 40 + col) =
                        make_float2(c[mt][nt][0], c[mt][nt][1]);
                if (rbase + 8 < n)
                    *(float2*)(C + (size_t)(rbase + 8) * 40 + col) =
                        make_float2(c[mt][nt][2], c[mt][nt][3]);
            }
        }
    }

    float ap[4] = {0.f, 0.f, 0.f, 0.f}, dp[4] = {0.f, 0.f, 0.f, 0.f};
#pragma unroll
    for (int mt = 0; mt < 2; mt++)
#pragma unroll
        for (int nt = 0; nt < 4; nt++) {
            int col = wn * 32 + nt * 8 + tcol;
            if (col < 40) {
                float s0 = __ldg(asrc + col), s1 = __ldg(asrc + col + 1);
                float d0 = __ldg(adst + col), d1 = __ldg(adst + col + 1);
                ap[mt * 2 + 0] += c[mt][nt][0] * s0 + c[mt][nt][1] * s1;
                ap[mt * 2 + 1] += c[mt][nt][2] * s0 + c[mt][nt][3] * s1;
                dp[mt * 2 + 0] += c[mt][nt][0] * d0 + c[mt][nt][1] * d1;
                dp[mt * 2 + 1] += c[mt][nt][2] * d0 + c[mt][nt][3] * d1;
            }
        }
#pragma unroll
    for (int off = 1; off <= 2; off <<= 1)
#pragma unroll
        for (int v = 0; v < 4; v++) {
            ap[v] += __shfl_xor_sync(0xffffffffu, ap[v], off);
            dp[v] += __shfl_xor_sync(0xffffffffu, dp[v], off);
        }
    if ((lane & 3) == 0) {
#pragma unroll
        for (int mt = 0; mt < 2; mt++)
#pragma unroll
            for (int rr = 0; rr < 2; rr++) {
                int rl = wm * 32 + mt * 16 + trow + rr * 8;
                atomicAdd(&salS[rl], ap[mt * 2 + rr]);
                atomicAdd(&salD[rl], dp[mt * 2 + rr]);
            }
    }
    __syncthreads();
    if (tid < 128 && r0 + tid < n) {
        als[r0 + tid] = salS[tid];
        ald[r0 + tid] = salD[tid];
    }
}

__device__ __forceinline__ float leaky(float v) {
    return v > 0.f ? v : NEG_SLOPE * v;
}

// ===== fused softmax-aggregation, H=4 C=32: 4 edges/iter, 8 lanes x 16ch per edge =====
__global__ __launch_bounds__(256) void fusedagg128_kernel(
    const int* __restrict__ rowptr, const int* __restrict__ csrsrc,
    const __half* __restrict__ h,
    const float* __restrict__ als, const float* __restrict__ ald,
    const float* __restrict__ bias,
    const float* __restrict__ bg, const float* __restrict__ bb,
    const float* __restrict__ bm, const float* __restrict__ bv,
    __half* __restrict__ fhi, __half* __restrict__ flo, int n)
{
    int d    = (blockIdx.x * blockDim.x + threadIdx.x) >> 5;
    int lane = threadIdx.x & 31;
    if (d >= n) return;
    int start = rowptr[d], end = rowptr[d + 1];
    int e    = lane >> 3;        // quarter (edge slot 0..3)
    int c8   = lane & 7;         // channel block: ch = c8*16 .. +15
    int head = c8 >> 1;

    float aldh = __ldg(ald + (size_t)d * 4 + head);

    float acc[16];
#pragma unroll
    for (int i = 0; i < 16; i++) acc[i] = 0.f;
    float denom = 0.f;

    for (int p = start + e; p < end; p += 4) {
        int s = __ldg(csrsrc + p);
        float a = __ldg(als + (size_t)s * 4 + head);
        const uint4* hp4 = (const uint4*)(h + (size_t)s * 128 + c8 * 16);
        uint4 u0 = hp4[0];
        uint4 u1 = hp4[1];
        float x = __expf(leaky(a + aldh));
        denom += x;
        float2 f;
        f = __half22float2(*(__half2*)&u0.x); acc[0] += x * f.x; acc[1] += x * f.y;
        f = __half22float2(*(__half2*)&u0.y); acc[2] += x * f.x; acc[3] += x * f.y;
        f = __half22float2(*(__half2*)&u0.z); acc[4] += x * f.x; acc[5] += x * f.y;
        f = __half22float2(*(__half2*)&u0.w); acc[6] += x * f.x; acc[7] += x * f.y;
        f = __half22float2(*(__half2*)&u1.x); acc[8] += x * f.x; acc[9] += x * f.y;
        f = __half22float2(*(__half2*)&u1.y); acc[10] += x * f.x; acc[11] += x * f.y;
        f = __half22float2(*(__half2*)&u1.z); acc[12] += x * f.x; acc[13] += x * f.y;
        f = __half22float2(*(__half2*)&u1.w); acc[14] += x * f.x; acc[15] += x * f.y;
    }

    // combine the four quarters (e occupies lane bits 3..4)
#pragma unroll
    for (int off = 8; off <= 16; off <<= 1) {
        denom += __shfl_xor_sync(0xffffffffu, denom, off);
#pragma unroll
        for (int i = 0; i < 16; i++)
            acc[i] += __shfl_xor_sync(0xffffffffu, acc[i], off);
    }

    if (e == 0) {
        float inv = 1.f / (denom + 1e-16f);
        int c = c8 * 16;
        float bi[16], gg[16], be[16], mm[16], vv[16];
#pragma unroll
        for (int q = 0; q < 4; q++) {
            *(float4*)(bi + q * 4) = *(const float4*)(bias + c + q * 4);
            *(float4*)(gg + q * 4) = *(const float4*)(bg + c + q * 4);
            *(float4*)(be + q * 4) = *(const float4*)(bb + c + q * 4);
            *(float4*)(mm + q * 4) = *(const float4*)(bm + c + q * 4);
            *(float4*)(vv + q * 4) = *(const float4*)(bv + c + q * 4);
        }
        __half h16[16], l16[16];
#pragma unroll
        for (int i = 0; i < 16; i++) {
            float r = fmaxf(acc[i] * inv + bi[i], 0.f);
            r = (r - mm[i]) * rsqrtf(vv[i] + BN_EPS) * gg[i] + be[i];
            h16[i] = __float2half_rn(r);
            l16[i] = __float2half_rn(r - __half2float(h16[i]));
        }
        *(uint4*)(fhi + (size_t)d * 128 + c)     = *(uint4*)h16;
        *(uint4*)(fhi + (size_t)d * 128 + c + 8) = *(uint4*)(h16 + 8);
        *(uint4*)(flo + (size_t)d * 128 + c)     = *(uint4*)l16;
        *(uint4*)(flo + (size_t)d * 128 + c + 8) = *(uint4*)(l16 + 8);
    }
}

// ===== fused layer-3 aggregation (H=1, C=40, fp32 h): 2 edges/iter =====
__global__ __launch_bounds__(256) void fusedagg40_kernel(
    const int* __restrict__ rowptr, const int* __restrict__ csrsrc,
    const float* __restrict__ h,
    const float* __restrict__ als, const float* __restrict__ ald,
    const float* __restrict__ bias,
    float* __restrict__ out, int n)
{
    int d    = (blockIdx.x * blockDim.x + threadIdx.x) >> 5;
    int lane = threadIdx.x & 31;
    if (d >= n) return;
    int start = rowptr[d], end = rowptr[d + 1];
    int e   = lane >> 4;
    int c16 = lane & 15;
    bool act = c16 < 10;

    float aldd = __ldg(ald + d);

    float4 acc = make_float4(0.f, 0.f, 0.f, 0.f);
    float denom = 0.f;
    for (int p = start + e; p < end; p += 2) {
        int s = __ldg(csrsrc + p);
        float x = __expf(leaky(__ldg(als + s) + aldd));
        denom += x;
        if (act) {
            float4 h0 = *(const float4*)(h + (size_t)s * 40 + c16 * 4);
            acc.x += x * h0.x; acc.y += x * h0.y;
            acc.z += x * h0.z; acc.w += x * h0.w;
        }
    }

    denom += __shfl_xor_sync(0xffffffffu, denom, 16);
    acc.x += __shfl_xor_sync(0xffffffffu, acc.x, 16);
    acc.y += __shfl_xor_sync(0xffffffffu, acc.y, 16);
    acc.z += __shfl_xor_sync(0xffffffffu, acc.z, 16);
    acc.w += __shfl_xor_sync(0xffffffffu, acc.w, 16);

    bool writer = (e == 0) && act;
    float inv = 1.f / (denom + 1e-16f);
    float4 v = make_float4(-INFINITY, -INFINITY, -INFINITY, -INFINITY);
    if (writer) {
        float4 bi = *(const float4*)(bias + c16 * 4);
        v.x = acc.x * inv + bi.x;
        v.y = acc.y * inv + bi.y;
        v.z = acc.z * inv + bi.z;
        v.w = acc.w * inv + bi.w;
    }
    float lm = fmaxf(fmaxf(v.x, v.y), fmaxf(v.z, v.w));
#pragma unroll
    for (int o = 16; o > 0; o >>= 1)
        lm = fmaxf(lm, __shfl_xor_sync(0xffffffffu, lm, o));
    float ls = 0.f;
    if (writer)
        ls = __expf(v.x - lm) + __expf(v.y - lm) + __expf(v.z - lm) + __expf(v.w - lm);
#pragma unroll
    for (int o = 16; o > 0; o >>= 1)
        ls += __shfl_xor_sync(0xffffffffu, ls, o);
    float lse = lm + logf(ls);
    if (writer) {
        float4 r = make_float4(v.x - lse, v.y - lse, v.z - lse, v.w - lse);
        *(float4*)(out + (size_t)d * 40 + c16 * 4) = r;
    }
}

// =========================== host launch ===========================
extern "C" void kernel_launch(void* const* d_in, const int* in_sizes, int n_in,
                              void* d_out, int out_size)
{
    const float* x      = (const float*)d_in[0];
    const int*   ei     = (const int*)  d_in[1];
    const float* W1     = (const float*)d_in[2];
    const float* a_src1 = (const float*)d_in[3];
    const float* a_dst1 = (const float*)d_in[4];
    const float* b1     = (const float*)d_in[5];
    const float* W2     = (const float*)d_in[6];
    const float* a_src2 = (const float*)d_in[7];
    const float* a_dst2 = (const float*)d_in[8];
    const float* b2     = (const float*)d_in[9];
    const float* W3     = (const float*)d_in[10];
    const float* a_src3 = (const float*)d_in[11];
    const float* a_dst3 = (const float*)d_in[12];
    const float* b3     = (const float*)d_in[13];
    const float* bn1_g  = (const float*)d_in[14];
    const float* bn1_b  = (const float*)d_in[15];
    const float* bn1_m  = (const float*)d_in[16];
    const float* bn1_v  = (const float*)d_in[17];
    const float* bn2_g  = (const float*)d_in[18];
    const float* bn2_b  = (const float*)d_in[19];
    const float* bn2_m  = (const float*)d_in[20];
    const float* bn2_v  = (const float*)d_in[21];
    float* out = (float*)d_out;

    int n    = in_sizes[0] / 128;   // 50000
    int E0   = in_sizes[1] / 2;     // 800000
    int Etot = E0 + n;

    float *p_hp, *p_als, *p_ald;
    __half *p_hph, *p_fhi, *p_flo;
    int *p_deg, *p_rank, *p_incl, *p_bsum, *p_rowptr, *p_csrsrc;
    cudaGetSymbolAddress((void**)&p_hp,     g_hp);
    cudaGetSymbolAddress((void**)&p_hph,    g_hph);
    cudaGetSymbolAddress((void**)&p_als,    g_al_src);
    cudaGetSymbolAddress((void**)&p_ald,    g_al_dst);
    cudaGetSymbolAddress((void**)&p_fhi,    g_fhi);
    cudaGetSymbolAddress((void**)&p_flo,    g_flo);
    cudaGetSymbolAddress((void**)&p_deg,    g_deg);
    cudaGetSymbolAddress((void**)&p_rank,   g_rank);
    cudaGetSymbolAddress((void**)&p_incl,   g_incl);
    cudaGetSymbolAddress((void**)&p_bsum,   g_bsum);
    cudaGetSymbolAddress((void**)&p_rowptr, g_rowptr);
    cudaGetSymbolAddress((void**)&p_csrsrc, g_csrsrc);

    cudaFuncSetAttribute(mma_gemm128_kernel<true>,
                         cudaFuncAttributeMaxDynamicSharedMemorySize, SM_TOT);
    cudaFuncSetAttribute(mma_gemm128_kernel<false>,
                         cudaFuncAttributeMaxDynamicSharedMemorySize, SM_TOT);
    cudaFuncSetAttribute(mma_gemm40_kernel,
                         cudaFuncAttributeMaxDynamicSharedMemorySize, SM4_TOT);

    static cudaStream_t s2 = nullptr;
    static cudaEvent_t evA = nullptr, evB = nullptr;
    if (s2 == nullptr) {
        cudaStreamCreateWithFlags(&s2, cudaStreamNonBlocking);
        cudaEventCreateWithFlags(&evA, cudaEventDisableTiming);
        cudaEventCreateWithFlags(&evB, cudaEventDisableTiming);
    }

    const int T = 256;
    int edgeBlocks = (Etot + T - 1) / T;
    int scanBlocks = (n + 1023) / 1024;
    int nodeBlocks = (n + T - 1) / T;
    int mmaBlocks  = (n + 127) / 128;
    int warpNodeBlocks = (n * 32 + T - 1) / T;

    // ---- fork: CSR build on s2, concurrent with layer-1 GEMM ----
    cudaEventRecord(evA, 0);
    cudaStreamWaitEvent(s2, evA, 0);

    cudaMemsetAsync(p_deg, 0, n * sizeof(int), s2);
    hist_kernel<<<edgeBlocks, T, 0, s2>>>(ei, E0, n, p_deg, p_rank);
    scan1_kernel<<<scanBlocks, 1024, 0, s2>>>(p_deg, p_incl, p_bsum, n);
    scan3_kernel<<<nodeBlocks, T, 0, s2>>>(p_incl, p_bsum, p_rowptr, n, scanBlocks);
    scatter_kernel<<<edgeBlocks, T, 0, s2>>>(ei, E0, n, p_rowptr, p_rank, p_csrsrc);
    cudaEventRecord(evB, s2);

    // ---------------- layer 1 ----------------
    mma_gemm128_kernel<true><<<mmaBlocks, T, SM_TOT>>>(
        x, nullptr, nullptr, W1, a_src1, a_dst1, p_hph, p_als, p_ald, n);

    cudaStreamWaitEvent(0, evB, 0);

    fusedagg128_kernel<<<warpNodeBlocks, T>>>(p_rowptr, p_csrsrc, p_hph, p_als, p_ald,
                                              b1, bn1_g, bn1_b, bn1_m, bn1_v,
                                              p_fhi, p_flo, n);

    // ---------------- layer 2 ----------------
    mma_gemm128_kernel<false><<<mmaBlocks, T, SM_TOT>>>(
        nullptr, p_fhi, p_flo, W2, a_src2, a_dst2, p_hph, p_als, p_ald, n);
    fusedagg128_kernel<<<warpNodeBlocks, T>>>(p_rowptr, p_csrsrc, p_hph, p_als, p_ald,
                                              b2, bn2_g, bn2_b, bn2_m, bn2_v,
                                              p_fhi, p_flo, n);

    // ---------------- layer 3 ----------------
    mma_gemm40_kernel<<<mmaBlocks, T, SM4_TOT>>>(p_fhi, p_flo, W3, a_src3, a_dst3,
                                                 p_hp, p_als, p_ald, n);
    fusedagg40_kernel<<<warpNodeBlocks, T>>>(p_rowptr, p_csrsrc, p_hp, p_als, p_ald,
                                             b3, out, n);
}

// round 11
// speedup vs baseline: 1.1064x; 1.1064x over previous
#include <cuda_runtime.h>
#include <cuda_bf16.h>
#include <cuda_fp16.h>
#include <math.h>
#include <stdint.h>

#define NN    50000
#define EE    800000
#define ETOT  (EE + NN)
#define NEG_SLOPE 0.2f
#define BN_EPS    1e-5f

// ---------------- scratch (device globals; no allocation) ----------------
__device__ float  g_hp[(size_t)NN * 40];       // layer-3 h (fp32)
__device__ __half g_hph[(size_t)NN * 128];     // layers 1/2 h (fp16, agg input)
__device__ __half g_fhi[(size_t)NN * 128];     // feat hi/lo (fp16 split, GEMM input)
__device__ __half g_flo[(size_t)NN * 128];
__device__ float g_al_src[NN * 4];
__device__ float g_al_dst[NN * 4];
__device__ int   g_deg[NN];
__device__ int   g_rank[ETOT];
__device__ int   g_incl[NN + 1024];
__device__ int   g_bsum[64];
__device__ int   g_rowptr[NN + 1];
__device__ int   g_csrsrc[ETOT];

__device__ __forceinline__ uint32_t smem_u32(const void* p) {
    uint32_t a;
    asm("{ .reg .u64 t; cvta.to.shared.u64 t, %1; cvt.u32.u64 %0, t; }" : "=r"(a) : "l"(p));
    return a;
}

// =========================== CSR build (rank-based, atomic-free scatter) ===========================
__global__ void hist_kernel(const int* __restrict__ ei, int E0, int n,
                            int* __restrict__ deg, int* __restrict__ rank)
{
    int t = blockIdx.x * blockDim.x + threadIdx.x;
    if (t >= E0 + n) return;
    int d = (t < E0) ? ei[E0 + t] : (t - E0);
    rank[t] = atomicAdd(&deg[d], 1);
}

__global__ void scan1_kernel(const int* __restrict__ deg, int* __restrict__ incl,
                             int* __restrict__ bsum, int n)
{
    __shared__ int sh[1024];
    int i = blockIdx.x * 1024 + threadIdx.x;
    int v = (i < n) ? deg[i] : 0;
    sh[threadIdx.x] = v;
    __syncthreads();
#pragma unroll
    for (int o = 1; o < 1024; o <<= 1) {
        int t = (threadIdx.x >= o) ? sh[threadIdx.x - o] : 0;
        __syncthreads();
        sh[threadIdx.x] += t;
        __syncthreads();
    }
    incl[i] = sh[threadIdx.x];
    if (threadIdx.x == 1023) bsum[blockIdx.x] = sh[1023];
}

__global__ void scan3_kernel(const int* __restrict__ incl, const int* __restrict__ bsum,
                             int* __restrict__ rowptr, int n, int nb)
{
    __shared__ int pref[64];
    if (threadIdx.x == 0) {
        int acc = 0;
        for (int b = 0; b < nb; b++) { pref[b] = acc; acc += bsum[b]; }
    }
    __syncthreads();
    int i = blockIdx.x * blockDim.x + threadIdx.x;
    if (i < n) rowptr[i + 1] = incl[i] + pref[i >> 10];
    if (i == 0) rowptr[0] = 0;
}

__global__ void scatter_kernel(const int* __restrict__ ei, int E0, int n,
                               const int* __restrict__ rowptr,
                               const int* __restrict__ rank,
                               int* __restrict__ csrsrc)
{
    int t = blockIdx.x * blockDim.x + threadIdx.x;
    if (t >= E0 + n) return;
    int s, d;
    if (t < E0) { s = ei[t]; d = ei[E0 + t]; }
    else        { s = d = t - E0; }
    csrsrc[rowptr[d] + rank[t]] = s;
}

// =========================== HMMA common (fp16, 2-pass split) ===========================
#define SROW    272
#define SM_AHI  0
#define SM_ALO  34816
#define SM_B    69632
#define SM_TOT  104448

#define SROWB   144
#define SM4_B   69632
#define SM4_SAL 88064
#define SM4_TOT 89088

__device__ __forceinline__ void ldsm_x4(uint32_t& r0, uint32_t& r1, uint32_t& r2,
                                        uint32_t& r3, uint32_t addr) {
    asm volatile("ldmatrix.sync.aligned.m8n8.x4.shared.b16 {%0,%1,%2,%3}, [%4];"
                 : "=r"(r0), "=r"(r1), "=r"(r2), "=r"(r3) : "r"(addr));
}
__device__ __forceinline__ void ldsm_x4_t(uint32_t& r0, uint32_t& r1, uint32_t& r2,
                                          uint32_t& r3, uint32_t addr) {
    asm volatile("ldmatrix.sync.aligned.m8n8.x4.trans.shared.b16 {%0,%1,%2,%3}, [%4];"
                 : "=r"(r0), "=r"(r1), "=r"(r2), "=r"(r3) : "r"(addr));
}
__device__ __forceinline__ void mma_f16(float* c, uint32_t a0, uint32_t a1, uint32_t a2,
                                        uint32_t a3, uint32_t b0, uint32_t b1) {
    asm volatile("mma.sync.aligned.m16n8k16.row.col.f32.f16.f16.f32 "
                 "{%0,%1,%2,%3}, {%4,%5,%6,%7}, {%8,%9}, {%0,%1,%2,%3};"
                 : "+f"(c[0]), "+f"(c[1]), "+f"(c[2]), "+f"(c[3])
                 : "r"(a0), "r"(a1), "r"(a2), "r"(a3), "r"(b0), "r"(b1));
}

__device__ __forceinline__ void split8h(const float* f, uint4* hi, uint4* lo) {
    __half h8[8], l8[8];
#pragma unroll
    for (int q = 0; q < 8; q++) {
        h8[q] = __float2half_rn(f[q]);
        l8[q] = __float2half_rn(f[q] - __half2float(h8[q]));
    }
    *hi = *(uint4*)h8;
    *lo = *(uint4*)l8;
}

// ===== wide GEMM 128x128 (A fp16 hi/lo, B fp16) + fused al dots; D fp16 =====
template<bool A32>
__global__ __launch_bounds__(256, 2) void mma_gemm128_kernel(
    const float* __restrict__ Af,
    const __half* __restrict__ Ahi, const __half* __restrict__ Alo,
    const float* __restrict__ W,
    const float* __restrict__ asrc, const float* __restrict__ adst,
    __half* __restrict__ hph, float* __restrict__ als, float* __restrict__ ald, int n)
{
    extern __shared__ char smem[];
    int tid = threadIdx.x, wid = tid >> 5, lane = tid & 31;
    int r0 = blockIdx.x * 128;

    for (int i = tid; i < 2048; i += 256) {
        int row = i >> 4, ch = i & 15;
        uint4 vh, vl;
        if (A32) {
            float f[8];
            if (r0 + row < n) {
                *(float4*)(f)     = *(const float4*)(Af + (size_t)(r0 + row) * 128 + ch * 8);
                *(float4*)(f + 4) = *(const float4*)(Af + (size_t)(r0 + row) * 128 + ch * 8 + 4);
            } else {
#pragma unroll
                for (int q = 0; q < 8; q++) f[q] = 0.f;
            }
            split8h(f, &vh, &vl);
        } else {
            if (r0 + row < n) {
                vh = *(const uint4*)(Ahi + (size_t)(r0 + row) * 128 + ch * 8);
                vl = *(const uint4*)(Alo + (size_t)(r0 + row) * 128 + ch * 8);
            } else {
                vh = make_uint4(0u, 0u, 0u, 0u); vl = vh;
            }
        }
        *(uint4*)(smem + SM_AHI + row * SROW + ch * 16) = vh;
        *(uint4*)(smem + SM_ALO + row * SROW + ch * 16) = vl;
    }
    for (int i = tid; i < 2048; i += 256) {
        int row = i >> 4, ch = i & 15;
        float f[8];
        *(float4*)(f)     = *(const float4*)(W + (size_t)row * 128 + ch * 8);
        *(float4*)(f + 4) = *(const float4*)(W + (size_t)row * 128 + ch * 8 + 4);
        __half h8[8];
#pragma unroll
        for (int q = 0; q < 8; q++) h8[q] = __float2half_rn(f[q]);
        *(uint4*)(smem + SM_B + row * SROW + ch * 16) = *(uint4*)h8;
    }
    __syncthreads();

    int wm = wid & 3;
    int wn = wid >> 2;
    uint32_t sb = smem_u32(smem);

    float c[2][8][4];
#pragma unroll
    for (int mt = 0; mt < 2; mt++)
#pragma unroll
        for (int nt = 0; nt < 8; nt++)
#pragma unroll
            for (int q = 0; q < 4; q++) c[mt][nt][q] = 0.f;

    int q  = lane >> 3;
    int lr = lane & 7;
    int a_row_in = wm * 32 + lr + (q & 1) * 8;
    int a_koff   = (q >> 1) * 8;
    int b_krow   = lr + (q & 1) * 8;
    int b_ncol0  = wn * 64 + (q >> 1) * 8;

    uint32_t bbase = sb + SM_B;
#pragma unroll
    for (int s = 0; s < 2; s++) {
        uint32_t abase = sb + ((s == 1) ? SM_ALO : SM_AHI);
#pragma unroll
        for (int ks = 0; ks < 8; ks++) {
            int k0 = ks * 16;
            uint32_t a0[4], a1[4];
            ldsm_x4(a0[0], a0[1], a0[2], a0[3],
                    abase + (a_row_in) * SROW + (k0 + a_koff) * 2);
            ldsm_x4(a1[0], a1[1], a1[2], a1[3],
                    abase + (a_row_in + 16) * SROW + (k0 + a_koff) * 2);
#pragma unroll
            for (int nt = 0; nt < 4; nt++) {
                uint32_t b[4];
                ldsm_x4_t(b[0], b[1], b[2], b[3],
                          bbase + (k0 + b_krow) * SROW + (b_ncol0 + nt * 16) * 2);
                mma_f16(c[0][nt * 2 + 0], a0[0], a0[1], a0[2], a0[3], b[0], b[1]);
                mma_f16(c[0][nt * 2 + 1], a0[0], a0[1], a0[2], a0[3], b[2], b[3]);
                mma_f16(c[1][nt * 2 + 0], a1[0], a1[1], a1[2], a1[3], b[0], b[1]);
                mma_f16(c[1][nt * 2 + 1], a1[0], a1[1], a1[2], a1[3], b[2], b[3]);
            }
        }
    }

    int trow = lane >> 2, tcol = (lane & 3) * 2;

#pragma unroll
    for (int mt = 0; mt < 2; mt++) {
        int rbase = r0 + wm * 32 + mt * 16 + trow;
#pragma unroll
        for (int nt = 0; nt < 8; nt++) {
            int col = wn * 64 + nt * 8 + tcol;
            if (rbase < n)
                *(__half2*)(hph + (size_t)rbase * 128 + col) =
                    __floats2half2_rn(c[mt][nt][0], c[mt][nt][1]);
            if (rbase + 8 < n)
                *(__half2*)(hph + (size_t)(rbase + 8) * 128 + col) =
                    __floats2half2_rn(c[mt][nt][2], c[mt][nt][3]);
        }
    }

    float ap[2][4], dp[2][4];
#pragma unroll
    for (int hh = 0; hh < 2; hh++)
#pragma unroll
        for (int v = 0; v < 4; v++) { ap[hh][v] = 0.f; dp[hh][v] = 0.f; }
#pragma unroll
    for (int nt = 0; nt < 8; nt++) {
        int col = wn * 64 + nt * 8 + tcol;
        int hh = nt >> 2;
        float s0 = __ldg(asrc + col), s1 = __ldg(asrc + col + 1);
        float d0 = __ldg(adst + col), d1 = __ldg(adst + col + 1);
#pragma unroll
        for (int mt = 0; mt < 2; mt++) {
            ap[hh][mt * 2 + 0] += c[mt][nt][0] * s0 + c[mt][nt][1] * s1;
            ap[hh][mt * 2 + 1] += c[mt][nt][2] * s0 + c[mt][nt][3] * s1;
            dp[hh][mt * 2 + 0] += c[mt][nt][0] * d0 + c[mt][nt][1] * d1;
            dp[hh][mt * 2 + 1] += c[mt][nt][2] * d0 + c[mt][nt][3] * d1;
        }
    }
#pragma unroll
    for (int off = 1; off <= 2; off <<= 1)
#pragma unroll
        for (int hh = 0; hh < 2; hh++)
#pragma unroll
            for (int v = 0; v < 4; v++) {
                ap[hh][v] += __shfl_xor_sync(0xffffffffu, ap[hh][v], off);
                dp[hh][v] += __shfl_xor_sync(0xffffffffu, dp[hh][v], off);
            }
    if ((lane & 3) == 0) {
#pragma unroll
        for (int mt = 0; mt < 2; mt++)
#pragma unroll
            for (int rr = 0; rr < 2; rr++) {
                int row = r0 + wm * 32 + mt * 16 + trow + rr * 8;
                int v = mt * 2 + rr;
                if (row < n) {
                    als[row * 4 + wn * 2 + 0] = ap[0][v];
                    als[row * 4 + wn * 2 + 1] = ap[1][v];
                    ald[row * 4 + wn * 2 + 0] = dp[0][v];
                    ald[row * 4 + wn * 2 + 1] = dp[1][v];
                }
            }
    }
}

// ===== layer-3 GEMM: [n,128] @ [128,40] (A fp16 hi/lo, B fp16, N padded 64) =====
__global__ __launch_bounds__(256, 2) void mma_gemm40_kernel(
    const __half* __restrict__ Ahi, const __half* __restrict__ Alo,
    const float* __restrict__ W,
    const float* __restrict__ asrc, const float* __restrict__ adst,
    float* __restrict__ C, float* __restrict__ als, float* __restrict__ ald, int n)
{
    extern __shared__ char smem[];
    float* salS = (float*)(smem + SM4_SAL);
    float* salD = salS + 128;
    int tid = threadIdx.x, wid = tid >> 5, lane = tid & 31;
    int r0 = blockIdx.x * 128;

    for (int i = tid; i < 2048; i += 256) {
        int row = i >> 4, ch = i & 15;
        uint4 vh, vl;
        if (r0 + row < n) {
            vh = *(const uint4*)(Ahi + (size_t)(r0 + row) * 128 + ch * 8);
            vl = *(const uint4*)(Alo + (size_t)(r0 + row) * 128 + ch * 8);
        } else {
            vh = make_uint4(0u, 0u, 0u, 0u); vl = vh;
        }
        *(uint4*)(smem + SM_AHI + row * SROW + ch * 16) = vh;
        *(uint4*)(smem + SM_ALO + row * SROW + ch * 16) = vl;
    }
    for (int i = tid; i < 8192; i += 256) {
        int row = i >> 6, cc = i & 63;
        float f = (cc < 40) ? W[(size_t)row * 40 + cc] : 0.f;
        *(__half*)(smem + SM4_B + row * SROWB + cc * 2) = __float2half_rn(f);
    }
    if (tid < 128) { salS[tid] = 0.f; salD[tid] = 0.f; }
    __syncthreads();

    int wm = wid & 3;
    int wn = wid >> 2;
    uint32_t sb = smem_u32(smem);

    float c[2][4][4];
#pragma unroll
    for (int mt = 0; mt < 2; mt++)
#pragma unroll
        for (int nt = 0; nt < 4; nt++)
#pragma unroll
            for (int q = 0; q < 4; q++) c[mt][nt][q] = 0.f;

    int q  = lane >> 3;
    int lr = lane & 7;
    int a_row_in = wm * 32 + lr + (q & 1) * 8;
    int a_koff   = (q >> 1) * 8;
    int b_krow   = lr + (q & 1) * 8;
    int b_ncol0  = wn * 32 + (q >> 1) * 8;

    uint32_t bbase = sb + SM4_B;
#pragma unroll
    for (int s = 0; s < 2; s++) {
        uint32_t abase = sb + ((s == 1) ? SM_ALO : SM_AHI);
#pragma unroll
        for (int ks = 0; ks < 8; ks++) {
            int k0 = ks * 16;
            uint32_t a0[4], a1[4];
            ldsm_x4(a0[0], a0[1], a0[2], a0[3],
                    abase + (a_row_in) * SROW + (k0 + a_koff) * 2);
            ldsm_x4(a1[0], a1[1], a1[2], a1[3],
                    abase + (a_row_in + 16) * SROW + (k0 + a_koff) * 2);
#pragma unroll
            for (int nt = 0; nt < 2; nt++) {
                uint32_t b[4];
                ldsm_x4_t(b[0], b[1], b[2], b[3],
                          bbase + (k0 + b_krow) * SROWB + (b_ncol0 + nt * 16) * 2);
                mma_f16(c[0][nt * 2 + 0], a0[0], a0[1], a0[2], a0[3], b[0], b[1]);
                mma_f16(c[0][nt * 2 + 1], a0[0], a0[1], a0[2], a0[3], b[2], b[3]);
                mma_f16(c[1][nt * 2 + 0], a1[0], a1[1], a1[2], a1[3], b[0], b[1]);
                mma_f16(c[1][nt * 2 + 1], a1[0], a1[1], a1[2], a1[3], b[2], b[3]);
            }
        }
    }

    int trow = lane >> 2, tcol = (lane & 3) * 2;

#pragma unroll
    for (int mt = 0; mt < 2; mt++) {
        int rbase = r0 + wm * 32 + mt * 16 + trow;
#pragma unroll
        for (int nt = 0; nt < 4; nt++) {
            int col = wn * 32 + nt * 8 + tcol;
            if (col < 40) {
                if (rbase < n)
                    *(float2*)(C + (size_t)rbase * 40 + col) =
                        make_float2(c[mt][nt][0], c[mt][nt][1]);
                if (rbase + 8 < n)
                    *(float2*)(C + (size_t)(rbase + 8) * 40 + col) =
                        make_float2(c[mt][nt][2], c[mt][nt][3]);
            }
        }
    }

    float ap[4] = {0.f, 0.f, 0.f, 0.f}, dp[4] = {0.f, 0.f, 0.f, 0.f};
#pragma unroll
    for (int mt = 0; mt < 2; mt++)
#pragma unroll
        for (int nt = 0; nt < 4; nt++) {
            int col = wn * 32 + nt * 8 + tcol;
            if (col < 40) {
                float s0 = __ldg(asrc + col), s1 = __ldg(asrc + col + 1);
                float d0 = __ldg(adst + col), d1 = __ldg(adst + col + 1);
                ap[mt * 2 + 0] += c[mt][nt][0] * s0 + c[mt][nt][1] * s1;
                ap[mt * 2 + 1] += c[mt][nt][2] * s0 + c[mt][nt][3] * s1;
                dp[mt * 2 + 0] += c[mt][nt][0] * d0 + c[mt][nt][1] * d1;
                dp[mt * 2 + 1] += c[mt][nt][2] * d0 + c[mt][nt][3] * d1;
            }
        }
#pragma unroll
    for (int off = 1; off <= 2; off <<= 1)
#pragma unroll
        for (int v = 0; v < 4; v++) {
            ap[v] += __shfl_xor_sync(0xffffffffu, ap[v], off);
            dp[v] += __shfl_xor_sync(0xffffffffu, dp[v], off);
        }
    if ((lane & 3) == 0) {
#pragma unroll
        for (int mt = 0; mt < 2; mt++)
#pragma unroll
            for (int rr = 0; rr < 2; rr++) {
                int rl = wm * 32 + mt * 16 + trow + rr * 8;
                atomicAdd(&salS[rl], ap[mt * 2 + rr]);
                atomicAdd(&salD[rl], dp[mt * 2 + rr]);
            }
    }
    __syncthreads();
    if (tid < 128 && r0 + tid < n) {
        als[r0 + tid] = salS[tid];
        ald[r0 + tid] = salD[tid];
    }
}

__device__ __forceinline__ float leaky(float v) {
    return v > 0.f ? v : NEG_SLOPE * v;
}

// ===== fused softmax-aggregation, H=4 C=32: 2 edges/iter, 16 lanes x 8ch per edge =====
__global__ __launch_bounds__(256) void fusedagg128_kernel(
    const int* __restrict__ rowptr, const int* __restrict__ csrsrc,
    const __half* __restrict__ h,
    const float* __restrict__ als, const float* __restrict__ ald,
    const float* __restrict__ bias,
    const float* __restrict__ bg, const float* __restrict__ bb,
    const float* __restrict__ bm, const float* __restrict__ bv,
    __half* __restrict__ fhi, __half* __restrict__ flo, int n)
{
    int d    = (blockIdx.x * blockDim.x + threadIdx.x) >> 5;
    int lane = threadIdx.x & 31;
    if (d >= n) return;
    int start = rowptr[d], end = rowptr[d + 1];
    int e    = lane >> 4;        // half (edge parity)
    int c16  = lane & 15;        // channel group: ch = c16*8 .. +7
    int head = c16 >> 2;

    float aldh = __ldg(ald + (size_t)d * 4 + head);

    float acc[8];
#pragma unroll
    for (int i = 0; i < 8; i++) acc[i] = 0.f;
    float denom = 0.f;

    for (int p = start + e; p < end; p += 2) {
        int s = __ldg(csrsrc + p);
        float a = __ldg(als + (size_t)s * 4 + head);
        uint4 u = *(const uint4*)(h + (size_t)s * 128 + c16 * 8);
        float x = __expf(leaky(a + aldh));
        denom += x;
        float2 f0 = __half22float2(*(__half2*)&u.x);
        float2 f1 = __half22float2(*(__half2*)&u.y);
        float2 f2 = __half22float2(*(__half2*)&u.z);
        float2 f3 = __half22float2(*(__half2*)&u.w);
        acc[0] += x * f0.x; acc[1] += x * f0.y;
        acc[2] += x * f1.x; acc[3] += x * f1.y;
        acc[4] += x * f2.x; acc[5] += x * f2.y;
        acc[6] += x * f3.x; acc[7] += x * f3.y;
    }

    // combine the two halves
    denom += __shfl_xor_sync(0xffffffffu, denom, 16);
#pragma unroll
    for (int i = 0; i < 8; i++)
        acc[i] += __shfl_xor_sync(0xffffffffu, acc[i], 16);

    if (e == 0) {
        float inv = 1.f / (denom + 1e-16f);
        int c = c16 * 8;
        float bi[8], gg[8], be[8], mm[8], vv[8];
        *(float4*)(bi)     = *(const float4*)(bias + c);
        *(float4*)(bi + 4) = *(const float4*)(bias + c + 4);
        *(float4*)(gg)     = *(const float4*)(bg + c);
        *(float4*)(gg + 4) = *(const float4*)(bg + c + 4);
        *(float4*)(be)     = *(const float4*)(bb + c);
        *(float4*)(be + 4) = *(const float4*)(bb + c + 4);
        *(float4*)(mm)     = *(const float4*)(bm + c);
        *(float4*)(mm + 4) = *(const float4*)(bm + c + 4);
        *(float4*)(vv)     = *(const float4*)(bv + c);
        *(float4*)(vv + 4) = *(const float4*)(bv + c + 4);
        __half h8[8], l8[8];
#pragma unroll
        for (int i = 0; i < 8; i++) {
            float r = fmaxf(acc[i] * inv + bi[i], 0.f);
            r = (r - mm[i]) * rsqrtf(vv[i] + BN_EPS) * gg[i] + be[i];
            h8[i] = __float2half_rn(r);
            l8[i] = __float2half_rn(r - __half2float(h8[i]));
        }
        *(uint4*)(fhi + (size_t)d * 128 + c) = *(uint4*)h8;
        *(uint4*)(flo + (size_t)d * 128 + c) = *(uint4*)l8;
    }
}

// ===== fused layer-3 aggregation (H=1, C=40, fp32 h): 2 edges/iter =====
__global__ __launch_bounds__(256) void fusedagg40_kernel(
    const int* __restrict__ rowptr, const int* __restrict__ csrsrc,
    const float* __restrict__ h,
    const float* __restrict__ als, const float* __restrict__ ald,
    const float* __restrict__ bias,
    float* __restrict__ out, int n)
{
    int d    = (blockIdx.x * blockDim.x + threadIdx.x) >> 5;
    int lane = threadIdx.x & 31;
    if (d >= n) return;
    int start = rowptr[d], end = rowptr[d + 1];
    int e   = lane >> 4;
    int c16 = lane & 15;
    bool act = c16 < 10;

    float aldd = __ldg(ald + d);

    float4 acc = make_float4(0.f, 0.f, 0.f, 0.f);
    float denom = 0.f;
    for (int p = start + e; p < end; p += 2) {
        int s = __ldg(csrsrc + p);
        float x = __expf(leaky(__ldg(als + s) + aldd));
        denom += x;
        if (act) {
            float4 h0 = *(const float4*)(h + (size_t)s * 40 + c16 * 4);
            acc.x += x * h0.x; acc.y += x * h0.y;
            acc.z += x * h0.z; acc.w += x * h0.w;
        }
    }

    denom += __shfl_xor_sync(0xffffffffu, denom, 16);
    acc.x += __shfl_xor_sync(0xffffffffu, acc.x, 16);
    acc.y += __shfl_xor_sync(0xffffffffu, acc.y, 16);
    acc.z += __shfl_xor_sync(0xffffffffu, acc.z, 16);
    acc.w += __shfl_xor_sync(0xffffffffu, acc.w, 16);

    bool writer = (e == 0) && act;
    float inv = 1.f / (denom + 1e-16f);
    float4 v = make_float4(-INFINITY, -INFINITY, -INFINITY, -INFINITY);
    if (writer) {
        float4 bi = *(const float4*)(bias + c16 * 4);
        v.x = acc.x * inv + bi.x;
        v.y = acc.y * inv + bi.y;
        v.z = acc.z * inv + bi.z;
        v.w = acc.w * inv + bi.w;
    }
    float lm = fmaxf(fmaxf(v.x, v.y), fmaxf(v.z, v.w));
#pragma unroll
    for (int o = 16; o > 0; o >>= 1)
        lm = fmaxf(lm, __shfl_xor_sync(0xffffffffu, lm, o));
    float ls = 0.f;
    if (writer)
        ls = __expf(v.x - lm) + __expf(v.y - lm) + __expf(v.z - lm) + __expf(v.w - lm);
#pragma unroll
    for (int o = 16; o > 0; o >>= 1)
        ls += __shfl_xor_sync(0xffffffffu, ls, o);
    float lse = lm + logf(ls);
    if (writer) {
        float4 r = make_float4(v.x - lse, v.y - lse, v.z - lse, v.w - lse);
        *(float4*)(out + (size_t)d * 40 + c16 * 4) = r;
    }
}

// =========================== host launch ===========================
extern "C" void kernel_launch(void* const* d_in, const int* in_sizes, int n_in,
                              void* d_out, int out_size)
{
    const float* x      = (const float*)d_in[0];
    const int*   ei     = (const int*)  d_in[1];
    const float* W1     = (const float*)d_in[2];
    const float* a_src1 = (const float*)d_in[3];
    const float* a_dst1 = (const float*)d_in[4];
    const float* b1     = (const float*)d_in[5];
    const float* W2     = (const float*)d_in[6];
    const float* a_src2 = (const float*)d_in[7];
    const float* a_dst2 = (const float*)d_in[8];
    const float* b2     = (const float*)d_in[9];
    const float* W3     = (const float*)d_in[10];
    const float* a_src3 = (const float*)d_in[11];
    const float* a_dst3 = (const float*)d_in[12];
    const float* b3     = (const float*)d_in[13];
    const float* bn1_g  = (const float*)d_in[14];
    const float* bn1_b  = (const float*)d_in[15];
    const float* bn1_m  = (const float*)d_in[16];
    const float* bn1_v  = (const float*)d_in[17];
    const float* bn2_g  = (const float*)d_in[18];
    const float* bn2_b  = (const float*)d_in[19];
    const float* bn2_m  = (const float*)d_in[20];
    const float* bn2_v  = (const float*)d_in[21];
    float* out = (float*)d_out;

    int n    = in_sizes[0] / 128;   // 50000
    int E0   = in_sizes[1] / 2;     // 800000
    int Etot = E0 + n;

    float *p_hp, *p_als, *p_ald;
    __half *p_hph, *p_fhi, *p_flo;
    int *p_deg, *p_rank, *p_incl, *p_bsum, *p_rowptr, *p_csrsrc;
    cudaGetSymbolAddress((void**)&p_hp,     g_hp);
    cudaGetSymbolAddress((void**)&p_hph,    g_hph);
    cudaGetSymbolAddress((void**)&p_als,    g_al_src);
    cudaGetSymbolAddress((void**)&p_ald,    g_al_dst);
    cudaGetSymbolAddress((void**)&p_fhi,    g_fhi);
    cudaGetSymbolAddress((void**)&p_flo,    g_flo);
    cudaGetSymbolAddress((void**)&p_deg,    g_deg);
    cudaGetSymbolAddress((void**)&p_rank,   g_rank);
    cudaGetSymbolAddress((void**)&p_incl,   g_incl);
    cudaGetSymbolAddress((void**)&p_bsum,   g_bsum);
    cudaGetSymbolAddress((void**)&p_rowptr, g_rowptr);
    cudaGetSymbolAddress((void**)&p_csrsrc, g_csrsrc);

    cudaFuncSetAttribute(mma_gemm128_kernel<true>,
                         cudaFuncAttributeMaxDynamicSharedMemorySize, SM_TOT);
    cudaFuncSetAttribute(mma_gemm128_kernel<false>,
                         cudaFuncAttributeMaxDynamicSharedMemorySize, SM_TOT);
    cudaFuncSetAttribute(mma_gemm40_kernel,
                         cudaFuncAttributeMaxDynamicSharedMemorySize, SM4_TOT);

    static cudaStream_t s2 = nullptr;
    static cudaEvent_t evA = nullptr, evB = nullptr;
    if (s2 == nullptr) {
        cudaStreamCreateWithFlags(&s2, cudaStreamNonBlocking);
        cudaEventCreateWithFlags(&evA, cudaEventDisableTiming);
        cudaEventCreateWithFlags(&evB, cudaEventDisableTiming);
    }

    const int T = 256;
    int edgeBlocks = (Etot + T - 1) / T;
    int scanBlocks = (n + 1023) / 1024;
    int nodeBlocks = (n + T - 1) / T;
    int mmaBlocks  = (n + 127) / 128;
    int warpNodeBlocks = (n * 32 + T - 1) / T;

    // ---- fork: CSR build on s2, concurrent with layer-1 GEMM ----
    cudaEventRecord(evA, 0);
    cudaStreamWaitEvent(s2, evA, 0);

    cudaMemsetAsync(p_deg, 0, n * sizeof(int), s2);
    hist_kernel<<<edgeBlocks, T, 0, s2>>>(ei, E0, n, p_deg, p_rank);
    scan1_kernel<<<scanBlocks, 1024, 0, s2>>>(p_deg, p_incl, p_bsum, n);
    scan3_kernel<<<nodeBlocks, T, 0, s2>>>(p_incl, p_bsum, p_rowptr, n, scanBlocks);
    scatter_kernel<<<edgeBlocks, T, 0, s2>>>(ei, E0, n, p_rowptr, p_rank, p_csrsrc);
    cudaEventRecord(evB, s2);

    // ---------------- layer 1 ----------------
    mma_gemm128_kernel<true><<<mmaBlocks, T, SM_TOT>>>(
        x, nullptr, nullptr, W1, a_src1, a_dst1, p_hph, p_als, p_ald, n);

    cudaStreamWaitEvent(0, evB, 0);

    fusedagg128_kernel<<<warpNodeBlocks, T>>>(p_rowptr, p_csrsrc, p_hph, p_als, p_ald,
                                              b1, bn1_g, bn1_b, bn1_m, bn1_v,
                                              p_fhi, p_flo, n);

    // ---------------- layer 2 ----------------
    mma_gemm128_kernel<false><<<mmaBlocks, T, SM_TOT>>>(
        nullptr, p_fhi, p_flo, W2, a_src2, a_dst2, p_hph, p_als, p_ald, n);
    fusedagg128_kernel<<<warpNodeBlocks, T>>>(p_rowptr, p_csrsrc, p_hph, p_als, p_ald,
                                              b2, bn2_g, bn2_b, bn2_m, bn2_v,
                                              p_fhi, p_flo, n);

    // ---------------- layer 3 ----------------
    mma_gemm40_kernel<<<mmaBlocks, T, SM4_TOT>>>(p_fhi, p_flo, W3, a_src3, a_dst3,
                                                 p_hp, p_als, p_ald, n);
    fusedagg40_kernel<<<warpNodeBlocks, T>>>(p_rowptr, p_csrsrc, p_hp, p_als, p_ald,
                                             b3, out, n);
}

// round 12
// speedup vs baseline: 1.1344x; 1.0253x over previous
#include <cuda_runtime.h>
#include <cuda_bf16.h>
#include <cuda_fp16.h>
#include <math.h>
#include <stdint.h>

#define NN    50000
#define EE    800000
#define ETOT  (EE + NN)
#define NEG_SLOPE 0.2f
#define BN_EPS    1e-5f

// ---------------- scratch (device globals; no allocation) ----------------
__device__ float  g_hp[(size_t)NN * 40];       // layer-3 h (fp32)
__device__ __half g_hph[(size_t)NN * 128];     // layers 1/2 h (fp16, agg input)
__device__ __half g_fhi[(size_t)NN * 128];     // feat hi/lo (fp16 split, GEMM input)
__device__ __half g_flo[(size_t)NN * 128];
__device__ float g_al_src[NN * 4];
__device__ float g_al_dst[NN * 4];
__device__ int   g_deg[NN];
__device__ int   g_rank[ETOT];
__device__ int   g_incl[NN + 1024];
__device__ int   g_bsum[64];
__device__ int   g_rowptr[NN + 1];
__device__ int   g_csrsrc[ETOT];

__device__ __forceinline__ uint32_t smem_u32(const void* p) {
    uint32_t a;
    asm("{ .reg .u64 t; cvta.to.shared.u64 t, %1; cvt.u32.u64 %0, t; }" : "=r"(a) : "l"(p));
    return a;
}

// =========================== CSR build (rank-based, atomic-free scatter) ===========================
__global__ void hist_kernel(const int* __restrict__ ei, int E0, int n,
                            int* __restrict__ deg, int* __restrict__ rank)
{
    int t = blockIdx.x * blockDim.x + threadIdx.x;
    if (t >= E0 + n) return;
    int d = (t < E0) ? ei[E0 + t] : (t - E0);
    rank[t] = atomicAdd(&deg[d], 1);
}

// shuffle-based block scan (2 barriers instead of 20)
__global__ void scan1_kernel(const int* __restrict__ deg, int* __restrict__ incl,
                             int* __restrict__ bsum, int n)
{
    __shared__ int wsum[32];
    int tid = threadIdx.x;
    int i = blockIdx.x * 1024 + tid;
    int lane = tid & 31, wid = tid >> 5;
    int s = (i < n) ? deg[i] : 0;
#pragma unroll
    for (int o = 1; o < 32; o <<= 1) {
        int t = __shfl_up_sync(0xffffffffu, s, o);
        if (lane >= o) s += t;
    }
    if (lane == 31) wsum[wid] = s;
    __syncthreads();
    if (wid == 0) {
        int w = wsum[lane];
#pragma unroll
        for (int o = 1; o < 32; o <<= 1) {
            int t = __shfl_up_sync(0xffffffffu, w, o);
            if (lane >= o) w += t;
        }
        wsum[lane] = w;
    }
    __syncthreads();
    int v = s + ((wid > 0) ? wsum[wid - 1] : 0);
    incl[i] = v;
    if (tid == 1023) bsum[blockIdx.x] = v;
}

__global__ void scan3_kernel(const int* __restrict__ incl, const int* __restrict__ bsum,
                             int* __restrict__ rowptr, int n, int nb)
{
    __shared__ int pref[64];
    if (threadIdx.x == 0) {
        int acc = 0;
        for (int b = 0; b < nb; b++) { pref[b] = acc; acc += bsum[b]; }
    }
    __syncthreads();
    int i = blockIdx.x * blockDim.x + threadIdx.x;
    if (i < n) rowptr[i + 1] = incl[i] + pref[i >> 10];
    if (i == 0) rowptr[0] = 0;
}

__global__ void scatter_kernel(const int* __restrict__ ei, int E0, int n,
                               const int* __restrict__ rowptr,
                               const int* __restrict__ rank,
                               int* __restrict__ csrsrc)
{
    int t = blockIdx.x * blockDim.x + threadIdx.x;
    if (t >= E0 + n) return;
    int s, d;
    if (t < E0) { s = ei[t]; d = ei[E0 + t]; }
    else        { s = d = t - E0; }
    csrsrc[rowptr[d] + rank[t]] = s;
}

// =========================== HMMA common (fp16, 2-pass split) ===========================
#define SROW    272
#define SM_AHI  0
#define SM_ALO  34816
#define SM_B    69632
#define SM_TOT  104448

#define SROWB   144
#define SM4_B   69632
#define SM4_SAL 88064
#define SM4_TOT 89088

__device__ __forceinline__ void ldsm_x4(uint32_t& r0, uint32_t& r1, uint32_t& r2,
                                        uint32_t& r3, uint32_t addr) {
    asm volatile("ldmatrix.sync.aligned.m8n8.x4.shared.b16 {%0,%1,%2,%3}, [%4];"
                 : "=r"(r0), "=r"(r1), "=r"(r2), "=r"(r3) : "r"(addr));
}
__device__ __forceinline__ void ldsm_x4_t(uint32_t& r0, uint32_t& r1, uint32_t& r2,
                                          uint32_t& r3, uint32_t addr) {
    asm volatile("ldmatrix.sync.aligned.m8n8.x4.trans.shared.b16 {%0,%1,%2,%3}, [%4];"
                 : "=r"(r0), "=r"(r1), "=r"(r2), "=r"(r3) : "r"(addr));
}
__device__ __forceinline__ void mma_f16(float* c, uint32_t a0, uint32_t a1, uint32_t a2,
                                        uint32_t a3, uint32_t b0, uint32_t b1) {
    asm volatile("mma.sync.aligned.m16n8k16.row.col.f32.f16.f16.f32 "
                 "{%0,%1,%2,%3}, {%4,%5,%6,%7}, {%8,%9}, {%0,%1,%2,%3};"
                 : "+f"(c[0]), "+f"(c[1]), "+f"(c[2]), "+f"(c[3])
                 : "r"(a0), "r"(a1), "r"(a2), "r"(a3), "r"(b0), "r"(b1));
}

__device__ __forceinline__ void split8h(const float* f, uint4* hi, uint4* lo) {
    __half h8[8], l8[8];
#pragma unroll
    for (int q = 0; q < 8; q++) {
        h8[q] = __float2half_rn(f[q]);
        l8[q] = __float2half_rn(f[q] - __half2float(h8[q]));
    }
    *hi = *(uint4*)h8;
    *lo = *(uint4*)l8;
}

// ===== wide GEMM 128x128 (A fp16 hi/lo, B fp16) + fused al dots; D fp16; chunked by r0off =====
template<bool A32>
__global__ __launch_bounds__(256, 2) void mma_gemm128_kernel(
    const float* __restrict__ Af,
    const __half* __restrict__ Ahi, const __half* __restrict__ Alo,
    const float* __restrict__ W,
    const float* __restrict__ asrc, const float* __restrict__ adst,
    __half* __restrict__ hph, float* __restrict__ als, float* __restrict__ ald,
    int r0off, int n)
{
    extern __shared__ char smem[];
    int tid = threadIdx.x, wid = tid >> 5, lane = tid & 31;
    int r0 = r0off + blockIdx.x * 128;

    for (int i = tid; i < 2048; i += 256) {
        int row = i >> 4, ch = i & 15;
        uint4 vh, vl;
        if (A32) {
            float f[8];
            if (r0 + row < n) {
                *(float4*)(f)     = *(const float4*)(Af + (size_t)(r0 + row) * 128 + ch * 8);
                *(float4*)(f + 4) = *(const float4*)(Af + (size_t)(r0 + row) * 128 + ch * 8 + 4);
            } else {
#pragma unroll
                for (int q = 0; q < 8; q++) f[q] = 0.f;
            }
            split8h(f, &vh, &vl);
        } else {
            if (r0 + row < n) {
                vh = *(const uint4*)(Ahi + (size_t)(r0 + row) * 128 + ch * 8);
                vl = *(const uint4*)(Alo + (size_t)(r0 + row) * 128 + ch * 8);
            } else {
                vh = make_uint4(0u, 0u, 0u, 0u); vl = vh;
            }
        }
        *(uint4*)(smem + SM_AHI + row * SROW + ch * 16) = vh;
        *(uint4*)(smem + SM_ALO + row * SROW + ch * 16) = vl;
    }
    for (int i = tid; i < 2048; i += 256) {
        int row = i >> 4, ch = i & 15;
        float f[8];
        *(float4*)(f)     = *(const float4*)(W + (size_t)row * 128 + ch * 8);
        *(float4*)(f + 4) = *(const float4*)(W + (size_t)row * 128 + ch * 8 + 4);
        __half h8[8];
#pragma unroll
        for (int q = 0; q < 8; q++) h8[q] = __float2half_rn(f[q]);
        *(uint4*)(smem + SM_B + row * SROW + ch * 16) = *(uint4*)h8;
    }
    __syncthreads();

    int wm = wid & 3;
    int wn = wid >> 2;
    uint32_t sb = smem_u32(smem);

    float c[2][8][4];
#pragma unroll
    for (int mt = 0; mt < 2; mt++)
#pragma unroll
        for (int nt = 0; nt < 8; nt++)
#pragma unroll
            for (int q = 0; q < 4; q++) c[mt][nt][q] = 0.f;

    int q  = lane >> 3;
    int lr = lane & 7;
    int a_row_in = wm * 32 + lr + (q & 1) * 8;
    int a_koff   = (q >> 1) * 8;
    int b_krow   = lr + (q & 1) * 8;
    int b_ncol0  = wn * 64 + (q >> 1) * 8;

    uint32_t bbase = sb + SM_B;
#pragma unroll
    for (int s = 0; s < 2; s++) {
        uint32_t abase = sb + ((s == 1) ? SM_ALO : SM_AHI);
#pragma unroll
        for (int ks = 0; ks < 8; ks++) {
            int k0 = ks * 16;
            uint32_t a0[4], a1[4];
            ldsm_x4(a0[0], a0[1], a0[2], a0[3],
                    abase + (a_row_in) * SROW + (k0 + a_koff) * 2);
            ldsm_x4(a1[0], a1[1], a1[2], a1[3],
                    abase + (a_row_in + 16) * SROW + (k0 + a_koff) * 2);
#pragma unroll
            for (int nt = 0; nt < 4; nt++) {
                uint32_t b[4];
                ldsm_x4_t(b[0], b[1], b[2], b[3],
                          bbase + (k0 + b_krow) * SROW + (b_ncol0 + nt * 16) * 2);
                mma_f16(c[0][nt * 2 + 0], a0[0], a0[1], a0[2], a0[3], b[0], b[1]);
                mma_f16(c[0][nt * 2 + 1], a0[0], a0[1], a0[2], a0[3], b[2], b[3]);
                mma_f16(c[1][nt * 2 + 0], a1[0], a1[1], a1[2], a1[3], b[0], b[1]);
                mma_f16(c[1][nt * 2 + 1], a1[0], a1[1], a1[2], a1[3], b[2], b[3]);
            }
        }
    }

    int trow = lane >> 2, tcol = (lane & 3) * 2;

#pragma unroll
    for (int mt = 0; mt < 2; mt++) {
        int rbase = r0 + wm * 32 + mt * 16 + trow;
#pragma unroll
        for (int nt = 0; nt < 8; nt++) {
            int col = wn * 64 + nt * 8 + tcol;
            if (rbase < n)
                *(__half2*)(hph + (size_t)rbase * 128 + col) =
                    __floats2half2_rn(c[mt][nt][0], c[mt][nt][1]);
            if (rbase + 8 < n)
                *(__half2*)(hph + (size_t)(rbase + 8) * 128 + col) =
                    __floats2half2_rn(c[mt][nt][2], c[mt][nt][3]);
        }
    }

    float ap[2][4], dp[2][4];
#pragma unroll
    for (int hh = 0; hh < 2; hh++)
#pragma unroll
        for (int v = 0; v < 4; v++) { ap[hh][v] = 0.f; dp[hh][v] = 0.f; }
#pragma unroll
    for (int nt = 0; nt < 8; nt++) {
        int col = wn * 64 + nt * 8 + tcol;
        int hh = nt >> 2;
        float s0 = __ldg(asrc + col), s1 = __ldg(asrc + col + 1);
        float d0 = __ldg(adst + col), d1 = __ldg(adst + col + 1);
#pragma unroll
        for (int mt = 0; mt < 2; mt++) {
            ap[hh][mt * 2 + 0] += c[mt][nt][0] * s0 + c[mt][nt][1] * s1;
            ap[hh][mt * 2 + 1] += c[mt][nt][2] * s0 + c[mt][nt][3] * s1;
            dp[hh][mt * 2 + 0] += c[mt][nt][0] * d0 + c[mt][nt][1] * d1;
            dp[hh][mt * 2 + 1] += c[mt][nt][2] * d0 + c[mt][nt][3] * d1;
        }
    }
#pragma unroll
    for (int off = 1; off <= 2; off <<= 1)
#pragma unroll
        for (int hh = 0; hh < 2; hh++)
#pragma unroll
            for (int v = 0; v < 4; v++) {
                ap[hh][v] += __shfl_xor_sync(0xffffffffu, ap[hh][v], off);
                dp[hh][v] += __shfl_xor_sync(0xffffffffu, dp[hh][v], off);
            }
    if ((lane & 3) == 0) {
#pragma unroll
        for (int mt = 0; mt < 2; mt++)
#pragma unroll
            for (int rr = 0; rr < 2; rr++) {
                int row = r0 + wm * 32 + mt * 16 + trow + rr * 8;
                int v = mt * 2 + rr;
                if (row < n) {
                    als[row * 4 + wn * 2 + 0] = ap[0][v];
                    als[row * 4 + wn * 2 + 1] = ap[1][v];
                    ald[row * 4 + wn * 2 + 0] = dp[0][v];
                    ald[row * 4 + wn * 2 + 1] = dp[1][v];
                }
            }
    }
}

// ===== layer-3 GEMM: [n,128] @ [128,40] (A fp16 hi/lo, B fp16, N padded 64); chunked =====
__global__ __launch_bounds__(256, 2) void mma_gemm40_kernel(
    const __half* __restrict__ Ahi, const __half* __restrict__ Alo,
    const float* __restrict__ W,
    const float* __restrict__ asrc, const float* __restrict__ adst,
    float* __restrict__ C, float* __restrict__ als, float* __restrict__ ald,
    int r0off, int n)
{
    extern __shared__ char smem[];
    float* salS = (float*)(smem + SM4_SAL);
    float* salD = salS + 128;
    int tid = threadIdx.x, wid = tid >> 5, lane = tid & 31;
    int r0 = r0off + blockIdx.x * 128;

    for (int i = tid; i < 2048; i += 256) {
        int row = i >> 4, ch = i & 15;
        uint4 vh, vl;
        if (r0 + row < n) {
            vh = *(const uint4*)(Ahi + (size_t)(r0 + row) * 128 + ch * 8);
            vl = *(const uint4*)(Alo + (size_t)(r0 + row) * 128 + ch * 8);
        } else {
            vh = make_uint4(0u, 0u, 0u, 0u); vl = vh;
        }
        *(uint4*)(smem + SM_AHI + row * SROW + ch * 16) = vh;
        *(uint4*)(smem + SM_ALO + row * SROW + ch * 16) = vl;
    }
    for (int i = tid; i < 8192; i += 256) {
        int row = i >> 6, cc = i & 63;
        float f = (cc < 40) ? W[(size_t)row * 40 + cc] : 0.f;
        *(__half*)(smem + SM4_B + row * SROWB + cc * 2) = __float2half_rn(f);
    }
    if (tid < 128) { salS[tid] = 0.f; salD[tid] = 0.f; }
    __syncthreads();

    int wm = wid & 3;
    int wn = wid >> 2;
    uint32_t sb = smem_u32(smem);

    float c[2][4][4];
#pragma unroll
    for (int mt = 0; mt < 2; mt++)
#pragma unroll
        for (int nt = 0; nt < 4; nt++)
#pragma unroll
            for (int q = 0; q < 4; q++) c[mt][nt][q] = 0.f;

    int q  = lane >> 3;
    int lr = lane & 7;
    int a_row_in = wm * 32 + lr + (q & 1) * 8;
    int a_koff   = (q >> 1) * 8;
    int b_krow   = lr + (q & 1) * 8;
    int b_ncol0  = wn * 32 + (q >> 1) * 8;

    uint32_t bbase = sb + SM4_B;
#pragma unroll
    for (int s = 0; s < 2; s++) {
        uint32_t abase = sb + ((s == 1) ? SM_ALO : SM_AHI);
#pragma unroll
        for (int ks = 0; ks < 8; ks++) {
            int k0 = ks * 16;
            uint32_t a0[4], a1[4];
            ldsm_x4(a0[0], a0[1], a0[2], a0[3],
                    abase + (a_row_in) * SROW + (k0 + a_koff) * 2);
            ldsm_x4(a1[0], a1[1], a1[2], a1[3],
                    abase + (a_row_in + 16) * SROW + (k0 + a_koff) * 2);
#pragma unroll
            for (int nt = 0; nt < 2; nt++) {
                uint32_t b[4];
                ldsm_x4_t(b[0], b[1], b[2], b[3],
                          bbase + (k0 + b_krow) * SROWB + (b_ncol0 + nt * 16) * 2);
                mma_f16(c[0][nt * 2 + 0], a0[0], a0[1], a0[2], a0[3], b[0], b[1]);
                mma_f16(c[0][nt * 2 + 1], a0[0], a0[1], a0[2], a0[3], b[2], b[3]);
                mma_f16(c[1][nt * 2 + 0], a1[0], a1[1], a1[2], a1[3], b[0], b[1]);
                mma_f16(c[1][nt * 2 + 1], a1[0], a1[1], a1[2], a1[3], b[2], b[3]);
            }
        }
    }

    int trow = lane >> 2, tcol = (lane & 3) * 2;

#pragma unroll
    for (int mt = 0; mt < 2; mt++) {
        int rbase = r0 + wm * 32 + mt * 16 + trow;
#pragma unroll
        for (int nt = 0; nt < 4; nt++) {
            int col = wn * 32 + nt * 8 + tcol;
            if (col < 40) {
                if (rbase < n)
                    *(float2*)(C + (size_t)rbase * 40 + col) =
                        make_float2(c[mt][nt][0], c[mt][nt][1]);
                if (rbase + 8 < n)
                    *(float2*)(C + (size_t)(rbase + 8) * 40 + col) =
                        make_float2(c[mt][nt][2], c[mt][nt][3]);
            }
        }
    }

    float ap[4] = {0.f, 0.f, 0.f, 0.f}, dp[4] = {0.f, 0.f, 0.f, 0.f};
#pragma unroll
    for (int mt = 0; mt < 2; mt++)
#pragma unroll
        for (int nt = 0; nt < 4; nt++) {
            int col = wn * 32 + nt * 8 + tcol;
            if (col < 40) {
                float s0 = __ldg(asrc + col), s1 = __ldg(asrc + col + 1);
                float d0 = __ldg(adst + col), d1 = __ldg(adst + col + 1);
                ap[mt * 2 + 0] += c[mt][nt][0] * s0 + c[mt][nt][1] * s1;
                ap[mt * 2 + 1] += c[mt][nt][2] * s0 + c[mt][nt][3] * s1;
                dp[mt * 2 + 0] += c[mt][nt][0] * d0 + c[mt][nt][1] * d1;
                dp[mt * 2 + 1] += c[mt][nt][2] * d0 + c[mt][nt][3] * d1;
            }
        }
#pragma unroll
    for (int off = 1; off <= 2; off <<= 1)
#pragma unroll
        for (int v = 0; v < 4; v++) {
            ap[v] += __shfl_xor_sync(0xffffffffu, ap[v], off);
            dp[v] += __shfl_xor_sync(0xffffffffu, dp[v], off);
        }
    if ((lane & 3) == 0) {
#pragma unroll
        for (int mt = 0; mt < 2; mt++)
#pragma unroll
            for (int rr = 0; rr < 2; rr++) {
                int rl = wm * 32 + mt * 16 + trow + rr * 8;
                atomicAdd(&salS[rl], ap[mt * 2 + rr]);
                atomicAdd(&salD[rl], dp[mt * 2 + rr]);
            }
    }
    __syncthreads();
    if (tid < 128 && r0 + tid < n) {
        als[r0 + tid] = salS[tid];
        ald[r0 + tid] = salD[tid];
    }
}

__device__ __forceinline__ float leaky(float v) {
    return v > 0.f ? v : NEG_SLOPE * v;
}

// ===== fused softmax-aggregation, H=4 C=32: 2 edges/iter; chunked by node offset =====
__global__ __launch_bounds__(256) void fusedagg128_kernel(
    const int* __restrict__ rowptr, const int* __restrict__ csrsrc,
    const __half* __restrict__ h,
    const float* __restrict__ als, const float* __restrict__ ald,
    const float* __restrict__ bias,
    const float* __restrict__ bg, const float* __restrict__ bb,
    const float* __restrict__ bm, const float* __restrict__ bv,
    __half* __restrict__ fhi, __half* __restrict__ flo, int noff, int ncnt)
{
    int d    = noff + ((blockIdx.x * blockDim.x + threadIdx.x) >> 5);
    int lane = threadIdx.x & 31;
    if (d >= noff + ncnt) return;
    int start = rowptr[d], end = rowptr[d + 1];
    int e    = lane >> 4;
    int c16  = lane & 15;
    int head = c16 >> 2;

    float aldh = __ldg(ald + (size_t)d * 4 + head);

    float acc[8];
#pragma unroll
    for (int i = 0; i < 8; i++) acc[i] = 0.f;
    float denom = 0.f;

    for (int p = start + e; p < end; p += 2) {
        int s = __ldg(csrsrc + p);
        float a = __ldg(als + (size_t)s * 4 + head);
        uint4 u = *(const uint4*)(h + (size_t)s * 128 + c16 * 8);
        float x = __expf(leaky(a + aldh));
        denom += x;
        float2 f0 = __half22float2(*(__half2*)&u.x);
        float2 f1 = __half22float2(*(__half2*)&u.y);
        float2 f2 = __half22float2(*(__half2*)&u.z);
        float2 f3 = __half22float2(*(__half2*)&u.w);
        acc[0] += x * f0.x; acc[1] += x * f0.y;
        acc[2] += x * f1.x; acc[3] += x * f1.y;
        acc[4] += x * f2.x; acc[5] += x * f2.y;
        acc[6] += x * f3.x; acc[7] += x * f3.y;
    }

    denom += __shfl_xor_sync(0xffffffffu, denom, 16);
#pragma unroll
    for (int i = 0; i < 8; i++)
        acc[i] += __shfl_xor_sync(0xffffffffu, acc[i], 16);

    if (e == 0) {
        float inv = 1.f / (denom + 1e-16f);
        int c = c16 * 8;
        float bi[8], gg[8], be[8], mm[8], vv[8];
        *(float4*)(bi)     = *(const float4*)(bias + c);
        *(float4*)(bi + 4) = *(const float4*)(bias + c + 4);
        *(float4*)(gg)     = *(const float4*)(bg + c);
        *(float4*)(gg + 4) = *(const float4*)(bg + c + 4);
        *(float4*)(be)     = *(const float4*)(bb + c);
        *(float4*)(be + 4) = *(const float4*)(bb + c + 4);
        *(float4*)(mm)     = *(const float4*)(bm + c);
        *(float4*)(mm + 4) = *(const float4*)(bm + c + 4);
        *(float4*)(vv)     = *(const float4*)(bv + c);
        *(float4*)(vv + 4) = *(const float4*)(bv + c + 4);
        __half h8[8], l8[8];
#pragma unroll
        for (int i = 0; i < 8; i++) {
            float r = fmaxf(acc[i] * inv + bi[i], 0.f);
            r = (r - mm[i]) * rsqrtf(vv[i] + BN_EPS) * gg[i] + be[i];
            h8[i] = __float2half_rn(r);
            l8[i] = __float2half_rn(r - __half2float(h8[i]));
        }
        *(uint4*)(fhi + (size_t)d * 128 + c) = *(uint4*)h8;
        *(uint4*)(flo + (size_t)d * 128 + c) = *(uint4*)l8;
    }
}

// ===== fused layer-3 aggregation (H=1, C=40, fp32 h): 2 edges/iter =====
__global__ __launch_bounds__(256) void fusedagg40_kernel(
    const int* __restrict__ rowptr, const int* __restrict__ csrsrc,
    const float* __restrict__ h,
    const float* __restrict__ als, const float* __restrict__ ald,
    const float* __restrict__ bias,
    float* __restrict__ out, int n)
{
    int d    = (blockIdx.x * blockDim.x + threadIdx.x) >> 5;
    int lane = threadIdx.x & 31;
    if (d >= n) return;
    int start = rowptr[d], end = rowptr[d + 1];
    int e   = lane >> 4;
    int c16 = lane & 15;
    bool act = c16 < 10;

    float aldd = __ldg(ald + d);

    float4 acc = make_float4(0.f, 0.f, 0.f, 0.f);
    float denom = 0.f;
    for (int p = start + e; p < end; p += 2) {
        int s = __ldg(csrsrc + p);
        float x = __expf(leaky(__ldg(als + s) + aldd));
        denom += x;
        if (act) {
            float4 h0 = *(const float4*)(h + (size_t)s * 40 + c16 * 4);
            acc.x += x * h0.x; acc.y += x * h0.y;
            acc.z += x * h0.z; acc.w += x * h0.w;
        }
    }

    denom += __shfl_xor_sync(0xffffffffu, denom, 16);
    acc.x += __shfl_xor_sync(0xffffffffu, acc.x, 16);
    acc.y += __shfl_xor_sync(0xffffffffu, acc.y, 16);
    acc.z += __shfl_xor_sync(0xffffffffu, acc.z, 16);
    acc.w += __shfl_xor_sync(0xffffffffu, acc.w, 16);

    bool writer = (e == 0) && act;
    float inv = 1.f / (denom + 1e-16f);
    float4 v = make_float4(-INFINITY, -INFINITY, -INFINITY, -INFINITY);
    if (writer) {
        float4 bi = *(const float4*)(bias + c16 * 4);
        v.x = acc.x * inv + bi.x;
        v.y = acc.y * inv + bi.y;
        v.z = acc.z * inv + bi.z;
        v.w = acc.w * inv + bi.w;
    }
    float lm = fmaxf(fmaxf(v.x, v.y), fmaxf(v.z, v.w));
#pragma unroll
    for (int o = 16; o > 0; o >>= 1)
        lm = fmaxf(lm, __shfl_xor_sync(0xffffffffu, lm, o));
    float ls = 0.f;
    if (writer)
        ls = __expf(v.x - lm) + __expf(v.y - lm) + __expf(v.z - lm) + __expf(v.w - lm);
#pragma unroll
    for (int o = 16; o > 0; o >>= 1)
        ls += __shfl_xor_sync(0xffffffffu, ls, o);
    float lse = lm + logf(ls);
    if (writer) {
        float4 r = make_float4(v.x - lse, v.y - lse, v.z - lse, v.w - lse);
        *(float4*)(out + (size_t)d * 40 + c16 * 4) = r;
    }
}

// =========================== host launch ===========================
extern "C" void kernel_launch(void* const* d_in, const int* in_sizes, int n_in,
                              void* d_out, int out_size)
{
    const float* x      = (const float*)d_in[0];
    const int*   ei     = (const int*)  d_in[1];
    const float* W1     = (const float*)d_in[2];
    const float* a_src1 = (const float*)d_in[3];
    const float* a_dst1 = (const float*)d_in[4];
    const float* b1     = (const float*)d_in[5];
    const float* W2     = (const float*)d_in[6];
    const float* a_src2 = (const float*)d_in[7];
    const float* a_dst2 = (const float*)d_in[8];
    const float* b2     = (const float*)d_in[9];
    const float* W3     = (const float*)d_in[10];
    const float* a_src3 = (const float*)d_in[11];
    const float* a_dst3 = (const float*)d_in[12];
    const float* b3     = (const float*)d_in[13];
    const float* bn1_g  = (const float*)d_in[14];
    const float* bn1_b  = (const float*)d_in[15];
    const float* bn1_m  = (const float*)d_in[16];
    const float* bn1_v  = (const float*)d_in[17];
    const float* bn2_g  = (const float*)d_in[18];
    const float* bn2_b  = (const float*)d_in[19];
    const float* bn2_m  = (const float*)d_in[20];
    const float* bn2_v  = (const float*)d_in[21];
    float* out = (float*)d_out;

    int n    = in_sizes[0] / 128;   // 50000
    int E0   = in_sizes[1] / 2;     // 800000
    int Etot = E0 + n;

    float *p_hp, *p_als, *p_ald;
    __half *p_hph, *p_fhi, *p_flo;
    int *p_deg, *p_rank, *p_incl, *p_bsum, *p_rowptr, *p_csrsrc;
    cudaGetSymbolAddress((void**)&p_hp,     g_hp);
    cudaGetSymbolAddress((void**)&p_hph,    g_hph);
    cudaGetSymbolAddress((void**)&p_als,    g_al_src);
    cudaGetSymbolAddress((void**)&p_ald,    g_al_dst);
    cudaGetSymbolAddress((void**)&p_fhi,    g_fhi);
    cudaGetSymbolAddress((void**)&p_flo,    g_flo);
    cudaGetSymbolAddress((void**)&p_deg,    g_deg);
    cudaGetSymbolAddress((void**)&p_rank,   g_rank);
    cudaGetSymbolAddress((void**)&p_incl,   g_incl);
    cudaGetSymbolAddress((void**)&p_bsum,   g_bsum);
    cudaGetSymbolAddress((void**)&p_rowptr, g_rowptr);
    cudaGetSymbolAddress((void**)&p_csrsrc, g_csrsrc);

    cudaFuncSetAttribute(mma_gemm128_kernel<true>,
                         cudaFuncAttributeMaxDynamicSharedMemorySize, SM_TOT);
    cudaFuncSetAttribute(mma_gemm128_kernel<false>,
                         cudaFuncAttributeMaxDynamicSharedMemorySize, SM_TOT);
    cudaFuncSetAttribute(mma_gemm40_kernel,
                         cudaFuncAttributeMaxDynamicSharedMemorySize, SM4_TOT);

    static cudaStream_t s2 = nullptr;
    static cudaEvent_t evA = nullptr, evB = nullptr, evG1 = nullptr;
    static cudaEvent_t evG2c0 = nullptr, evG2c1 = nullptr, ev40c1 = nullptr;
    if (s2 == nullptr) {
        cudaStreamCreateWithFlags(&s2, cudaStreamNonBlocking);
        cudaEventCreateWithFlags(&evA, cudaEventDisableTiming);
        cudaEventCreateWithFlags(&evB, cudaEventDisableTiming);
        cudaEventCreateWithFlags(&evG1, cudaEventDisableTiming);
        cudaEventCreateWithFlags(&evG2c0, cudaEventDisableTiming);
        cudaEventCreateWithFlags(&evG2c1, cudaEventDisableTiming);
        cudaEventCreateWithFlags(&ev40c1, cudaEventDisableTiming);
    }

    const int T = 256;
    int edgeBlocks = (Etot + T - 1) / T;
    int scanBlocks = (n + 1023) / 1024;
    int nodeBlocks = (n + T - 1) / T;
    int mmaBlocks  = (n + 127) / 128;
    int warpNodeBlocks = (n * 32 + T - 1) / T;

    // chunk split (128-aligned)
    int half = ((n / 2 + 127) / 128) * 128;   // 25088
    int c1   = n - half;
    int gB0  = half / 128;
    int gB1  = (c1 + 127) / 128;
    int aB0  = (half * 32 + T - 1) / T;
    int aB1  = (c1 * 32 + T - 1) / T;

    // ---- fork: CSR build on s2, concurrent with layer-1 GEMM ----
    cudaEventRecord(evA, 0);
    cudaStreamWaitEvent(s2, evA, 0);

    cudaMemsetAsync(p_deg, 0, n * sizeof(int), s2);
    hist_kernel<<<edgeBlocks, T, 0, s2>>>(ei, E0, n, p_deg, p_rank);
    scan1_kernel<<<scanBlocks, 1024, 0, s2>>>(p_deg, p_incl, p_bsum, n);
    scan3_kernel<<<nodeBlocks, T, 0, s2>>>(p_incl, p_bsum, p_rowptr, n, scanBlocks);
    scatter_kernel<<<edgeBlocks, T, 0, s2>>>(ei, E0, n, p_rowptr, p_rank, p_csrsrc);

    // ---------------- layer 1 GEMM (full, on s0) ----------------
    mma_gemm128_kernel<true><<<mmaBlocks, T, SM_TOT>>>(
        x, nullptr, nullptr, W1, a_src1, a_dst1, p_hph, p_als, p_ald, 0, n);
    cudaEventRecord(evG1, 0);
    cudaEventRecord(evB, s2);

    // ---------------- pipelined layers: chunk0 on s0, chunk1 on s2 ----------------
    // agg1
    cudaStreamWaitEvent(0, evB, 0);      // s0 needs CSR
    cudaStreamWaitEvent(s2, evG1, 0);    // s2 needs gemm1
    fusedagg128_kernel<<<aB0, T>>>(p_rowptr, p_csrsrc, p_hph, p_als, p_ald,
                                   b1, bn1_g, bn1_b, bn1_m, bn1_v,
                                   p_fhi, p_flo, 0, half);
    fusedagg128_kernel<<<aB1, T, 0, s2>>>(p_rowptr, p_csrsrc, p_hph, p_als, p_ald,
                                          b1, bn1_g, bn1_b, bn1_m, bn1_v,
                                          p_fhi, p_flo, half, c1);
    // gemm2 chunks (each needs only its own feat rows)
    mma_gemm128_kernel<false><<<gB0, T, SM_TOT>>>(
        nullptr, p_fhi, p_flo, W2, a_src2, a_dst2, p_hph, p_als, p_ald, 0, n);
    cudaEventRecord(evG2c0, 0);
    mma_gemm128_kernel<false><<<gB1, T, SM_TOT, s2>>>(
        nullptr, p_fhi, p_flo, W2, a_src2, a_dst2, p_hph, p_als, p_ald, half, n);
    cudaEventRecord(evG2c1, s2);

    // agg2 (needs BOTH gemm2 chunks)
    cudaStreamWaitEvent(0, evG2c1, 0);
    cudaStreamWaitEvent(s2, evG2c0, 0);
    fusedagg128_kernel<<<aB0, T>>>(p_rowptr, p_csrsrc, p_hph, p_als, p_ald,
                                   b2, bn2_g, bn2_b, bn2_m, bn2_v,
                                   p_fhi, p_flo, 0, half);
    fusedagg128_kernel<<<aB1, T, 0, s2>>>(p_rowptr, p_csrsrc, p_hph, p_als, p_ald,
                                          b2, bn2_g, bn2_b, bn2_m, bn2_v,
                                          p_fhi, p_flo, half, c1);
    // gemm40 chunks
    mma_gemm40_kernel<<<gB0, T, SM4_TOT>>>(p_fhi, p_flo, W3, a_src3, a_dst3,
                                           p_hp, p_als, p_ald, 0, n);
    mma_gemm40_kernel<<<gB1, T, SM4_TOT, s2>>>(p_fhi, p_flo, W3, a_src3, a_dst3,
                                               p_hp, p_als, p_ald, half, n);
    cudaEventRecord(ev40c1, s2);

    // agg40 (full, needs both gemm40 chunks)
    cudaStreamWaitEvent(0, ev40c1, 0);
    fusedagg40_kernel<<<warpNodeBlocks, T>>>(p_rowptr, p_csrsrc, p_hp, p_als, p_ald,
                                             b3, out, n);
}

// round 13
// speedup vs baseline: 1.3290x; 1.1716x over previous
#include <cuda_runtime.h>
#include <cuda_bf16.h>
#include <cuda_fp16.h>
#include <math.h>
#include <stdint.h>

#define NN    50000
#define EE    800000
#define ETOT  (EE + NN)
#define NEG_SLOPE 0.2f
#define BN_EPS    1e-5f

// ---------------- scratch (device globals; no allocation) ----------------
__device__ float  g_hp[(size_t)NN * 40];       // layer-3 h (fp32)
__device__ __half g_hph[(size_t)NN * 128];     // layers 1/2 h (fp16, agg input)
__device__ __half g_feat[(size_t)NN * 128];    // feat (fp16, GEMM input)
__device__ float g_al_src[NN * 4];
__device__ float g_al_dst[NN * 4];
__device__ int   g_deg[NN];
__device__ int   g_rank[ETOT];
__device__ int   g_incl[NN + 1024];
__device__ int   g_bsum[64];
__device__ int   g_rowptr[NN + 1];
__device__ int   g_csrsrc[ETOT];

__device__ __forceinline__ uint32_t smem_u32(const void* p) {
    uint32_t a;
    asm("{ .reg .u64 t; cvta.to.shared.u64 t, %1; cvt.u32.u64 %0, t; }" : "=r"(a) : "l"(p));
    return a;
}

// =========================== CSR build (rank-based, atomic-free scatter) ===========================
__global__ void hist_kernel(const int* __restrict__ ei, int E0, int n,
                            int* __restrict__ deg, int* __restrict__ rank)
{
    int t = blockIdx.x * blockDim.x + threadIdx.x;
    if (t >= E0 + n) return;
    int d = (t < E0) ? ei[E0 + t] : (t - E0);
    rank[t] = atomicAdd(&deg[d], 1);
}

__global__ void scan1_kernel(const int* __restrict__ deg, int* __restrict__ incl,
                             int* __restrict__ bsum, int n)
{
    __shared__ int wsum[32];
    int tid = threadIdx.x;
    int i = blockIdx.x * 1024 + tid;
    int lane = tid & 31, wid = tid >> 5;
    int s = (i < n) ? deg[i] : 0;
#pragma unroll
    for (int o = 1; o < 32; o <<= 1) {
        int t = __shfl_up_sync(0xffffffffu, s, o);
        if (lane >= o) s += t;
    }
    if (lane == 31) wsum[wid] = s;
    __syncthreads();
    if (wid == 0) {
        int w = wsum[lane];
#pragma unroll
        for (int o = 1; o < 32; o <<= 1) {
            int t = __shfl_up_sync(0xffffffffu, w, o);
            if (lane >= o) w += t;
        }
        wsum[lane] = w;
    }
    __syncthreads();
    int v = s + ((wid > 0) ? wsum[wid - 1] : 0);
    incl[i] = v;
    if (tid == 1023) bsum[blockIdx.x] = v;
}

__global__ void scan3_kernel(const int* __restrict__ incl, const int* __restrict__ bsum,
                             int* __restrict__ rowptr, int n, int nb)
{
    __shared__ int pref[64];
    if (threadIdx.x == 0) {
        int acc = 0;
        for (int b = 0; b < nb; b++) { pref[b] = acc; acc += bsum[b]; }
    }
    __syncthreads();
    int i = blockIdx.x * blockDim.x + threadIdx.x;
    if (i < n) rowptr[i + 1] = incl[i] + pref[i >> 10];
    if (i == 0) rowptr[0] = 0;
}

__global__ void scatter_kernel(const int* __restrict__ ei, int E0, int n,
                               const int* __restrict__ rowptr,
                               const int* __restrict__ rank,
                               int* __restrict__ csrsrc)
{
    int t = blockIdx.x * blockDim.x + threadIdx.x;
    if (t >= E0 + n) return;
    int s, d;
    if (t < E0) { s = ei[t]; d = ei[E0 + t]; }
    else        { s = d = t - E0; }
    csrsrc[rowptr[d] + rank[t]] = s;
}

// =========================== HMMA common (single fp16) ===========================
#define SROW    272
#define SM_A    0
#define SM_B    34816
#define SM_TOT  69632

#define SROWB   144
#define SM4_B   34816
#define SM4_SAL 53248
#define SM4_TOT 54272

__device__ __forceinline__ void ldsm_x4(uint32_t& r0, uint32_t& r1, uint32_t& r2,
                                        uint32_t& r3, uint32_t addr) {
    asm volatile("ldmatrix.sync.aligned.m8n8.x4.shared.b16 {%0,%1,%2,%3}, [%4];"
                 : "=r"(r0), "=r"(r1), "=r"(r2), "=r"(r3) : "r"(addr));
}
__device__ __forceinline__ void ldsm_x4_t(uint32_t& r0, uint32_t& r1, uint32_t& r2,
                                          uint32_t& r3, uint32_t addr) {
    asm volatile("ldmatrix.sync.aligned.m8n8.x4.trans.shared.b16 {%0,%1,%2,%3}, [%4];"
                 : "=r"(r0), "=r"(r1), "=r"(r2), "=r"(r3) : "r"(addr));
}
__device__ __forceinline__ void mma_f16(float* c, uint32_t a0, uint32_t a1, uint32_t a2,
                                        uint32_t a3, uint32_t b0, uint32_t b1) {
    asm volatile("mma.sync.aligned.m16n8k16.row.col.f32.f16.f16.f32 "
                 "{%0,%1,%2,%3}, {%4,%5,%6,%7}, {%8,%9}, {%0,%1,%2,%3};"
                 : "+f"(c[0]), "+f"(c[1]), "+f"(c[2]), "+f"(c[3])
                 : "r"(a0), "r"(a1), "r"(a2), "r"(a3), "r"(b0), "r"(b1));
}

// ===== wide GEMM 128x128 (A fp16, B fp16) + fused al dots; D fp16; chunked by r0off =====
template<bool A32>
__global__ __launch_bounds__(256, 2) void mma_gemm128_kernel(
    const float* __restrict__ Af,
    const __half* __restrict__ Ah,
    const float* __restrict__ W,
    const float* __restrict__ asrc, const float* __restrict__ adst,
    __half* __restrict__ hph, float* __restrict__ als, float* __restrict__ ald,
    int r0off, int n)
{
    extern __shared__ char smem[];
    int tid = threadIdx.x, wid = tid >> 5, lane = tid & 31;
    int r0 = r0off + blockIdx.x * 128;

    for (int i = tid; i < 2048; i += 256) {
        int row = i >> 4, ch = i & 15;
        uint4 vh;
        if (A32) {
            float f[8];
            if (r0 + row < n) {
                *(float4*)(f)     = *(const float4*)(Af + (size_t)(r0 + row) * 128 + ch * 8);
                *(float4*)(f + 4) = *(const float4*)(Af + (size_t)(r0 + row) * 128 + ch * 8 + 4);
            } else {
#pragma unroll
                for (int q = 0; q < 8; q++) f[q] = 0.f;
            }
            __half h8[8];
#pragma unroll
            for (int q = 0; q < 8; q++) h8[q] = __float2half_rn(f[q]);
            vh = *(uint4*)h8;
        } else {
            vh = (r0 + row < n) ? *(const uint4*)(Ah + (size_t)(r0 + row) * 128 + ch * 8)
                                : make_uint4(0u, 0u, 0u, 0u);
        }
        *(uint4*)(smem + SM_A + row * SROW + ch * 16) = vh;
    }
    for (int i = tid; i < 2048; i += 256) {
        int row = i >> 4, ch = i & 15;
        float f[8];
        *(float4*)(f)     = *(const float4*)(W + (size_t)row * 128 + ch * 8);
        *(float4*)(f + 4) = *(const float4*)(W + (size_t)row * 128 + ch * 8 + 4);
        __half h8[8];
#pragma unroll
        for (int q = 0; q < 8; q++) h8[q] = __float2half_rn(f[q]);
        *(uint4*)(smem + SM_B + row * SROW + ch * 16) = *(uint4*)h8;
    }
    __syncthreads();

    int wm = wid & 3;
    int wn = wid >> 2;
    uint32_t sb = smem_u32(smem);

    float c[2][8][4];
#pragma unroll
    for (int mt = 0; mt < 2; mt++)
#pragma unroll
        for (int nt = 0; nt < 8; nt++)
#pragma unroll
            for (int q = 0; q < 4; q++) c[mt][nt][q] = 0.f;

    int q  = lane >> 3;
    int lr = lane & 7;
    int a_row_in = wm * 32 + lr + (q & 1) * 8;
    int a_koff   = (q >> 1) * 8;
    int b_krow   = lr + (q & 1) * 8;
    int b_ncol0  = wn * 64 + (q >> 1) * 8;

    uint32_t abase = sb + SM_A;
    uint32_t bbase = sb + SM_B;
#pragma unroll
    for (int ks = 0; ks < 8; ks++) {
        int k0 = ks * 16;
        uint32_t a0[4], a1[4];
        ldsm_x4(a0[0], a0[1], a0[2], a0[3],
                abase + (a_row_in) * SROW + (k0 + a_koff) * 2);
        ldsm_x4(a1[0], a1[1], a1[2], a1[3],
                abase + (a_row_in + 16) * SROW + (k0 + a_koff) * 2);
#pragma unroll
        for (int nt = 0; nt < 4; nt++) {
            uint32_t b[4];
            ldsm_x4_t(b[0], b[1], b[2], b[3],
                      bbase + (k0 + b_krow) * SROW + (b_ncol0 + nt * 16) * 2);
            mma_f16(c[0][nt * 2 + 0], a0[0], a0[1], a0[2], a0[3], b[0], b[1]);
            mma_f16(c[0][nt * 2 + 1], a0[0], a0[1], a0[2], a0[3], b[2], b[3]);
            mma_f16(c[1][nt * 2 + 0], a1[0], a1[1], a1[2], a1[3], b[0], b[1]);
            mma_f16(c[1][nt * 2 + 1], a1[0], a1[1], a1[2], a1[3], b[2], b[3]);
        }
    }

    int trow = lane >> 2, tcol = (lane & 3) * 2;

#pragma unroll
    for (int mt = 0; mt < 2; mt++) {
        int rbase = r0 + wm * 32 + mt * 16 + trow;
#pragma unroll
        for (int nt = 0; nt < 8; nt++) {
            int col = wn * 64 + nt * 8 + tcol;
            if (rbase < n)
                *(__half2*)(hph + (size_t)rbase * 128 + col) =
                    __floats2half2_rn(c[mt][nt][0], c[mt][nt][1]);
            if (rbase + 8 < n)
                *(__half2*)(hph + (size_t)(rbase + 8) * 128 + col) =
                    __floats2half2_rn(c[mt][nt][2], c[mt][nt][3]);
        }
    }

    float ap[2][4], dp[2][4];
#pragma unroll
    for (int hh = 0; hh < 2; hh++)
#pragma unroll
        for (int v = 0; v < 4; v++) { ap[hh][v] = 0.f; dp[hh][v] = 0.f; }
#pragma unroll
    for (int nt = 0; nt < 8; nt++) {
        int col = wn * 64 + nt * 8 + tcol;
        int hh = nt >> 2;
        float s0 = __ldg(asrc + col), s1 = __ldg(asrc + col + 1);
        float d0 = __ldg(adst + col), d1 = __ldg(adst + col + 1);
#pragma unroll
        for (int mt = 0; mt < 2; mt++) {
            ap[hh][mt * 2 + 0] += c[mt][nt][0] * s0 + c[mt][nt][1] * s1;
            ap[hh][mt * 2 + 1] += c[mt][nt][2] * s0 + c[mt][nt][3] * s1;
            dp[hh][mt * 2 + 0] += c[mt][nt][0] * d0 + c[mt][nt][1] * d1;
            dp[hh][mt * 2 + 1] += c[mt][nt][2] * d0 + c[mt][nt][3] * d1;
        }
    }
#pragma unroll
    for (int off = 1; off <= 2; off <<= 1)
#pragma unroll
        for (int hh = 0; hh < 2; hh++)
#pragma unroll
            for (int v = 0; v < 4; v++) {
                ap[hh][v] += __shfl_xor_sync(0xffffffffu, ap[hh][v], off);
                dp[hh][v] += __shfl_xor_sync(0xffffffffu, dp[hh][v], off);
            }
    if ((lane & 3) == 0) {
#pragma unroll
        for (int mt = 0; mt < 2; mt++)
#pragma unroll
            for (int rr = 0; rr < 2; rr++) {
                int row = r0 + wm * 32 + mt * 16 + trow + rr * 8;
                int v = mt * 2 + rr;
                if (row < n) {
                    als[row * 4 + wn * 2 + 0] = ap[0][v];
                    als[row * 4 + wn * 2 + 1] = ap[1][v];
                    ald[row * 4 + wn * 2 + 0] = dp[0][v];
                    ald[row * 4 + wn * 2 + 1] = dp[1][v];
                }
            }
    }
}

// ===== layer-3 GEMM: [n,128] @ [128,40] (A fp16, B fp16, N padded 64); chunked =====
__global__ __launch_bounds__(256, 2) void mma_gemm40_kernel(
    const __half* __restrict__ Ah,
    const float* __restrict__ W,
    const float* __restrict__ asrc, const float* __restrict__ adst,
    float* __restrict__ C, float* __restrict__ als, float* __restrict__ ald,
    int r0off, int n)
{
    extern __shared__ char smem[];
    float* salS = (float*)(smem + SM4_SAL);
    float* salD = salS + 128;
    int tid = threadIdx.x, wid = tid >> 5, lane = tid & 31;
    int r0 = r0off + blockIdx.x * 128;

    for (int i = tid; i < 2048; i += 256) {
        int row = i >> 4, ch = i & 15;
        uint4 vh = (r0 + row < n) ? *(const uint4*)(Ah + (size_t)(r0 + row) * 128 + ch * 8)
                                  : make_uint4(0u, 0u, 0u, 0u);
        *(uint4*)(smem + SM_A + row * SROW + ch * 16) = vh;
    }
    for (int i = tid; i < 8192; i += 256) {
        int row = i >> 6, cc = i & 63;
        float f = (cc < 40) ? W[(size_t)row * 40 + cc] : 0.f;
        *(__half*)(smem + SM4_B + row * SROWB + cc * 2) = __float2half_rn(f);
    }
    if (tid < 128) { salS[tid] = 0.f; salD[tid] = 0.f; }
    __syncthreads();

    int wm = wid & 3;
    int wn = wid >> 2;
    uint32_t sb = smem_u32(smem);

    float c[2][4][4];
#pragma unroll
    for (int mt = 0; mt < 2; mt++)
#pragma unroll
        for (int nt = 0; nt < 4; nt++)
#pragma unroll
            for (int q = 0; q < 4; q++) c[mt][nt][q] = 0.f;

    int q  = lane >> 3;
    int lr = lane & 7;
    int a_row_in = wm * 32 + lr + (q & 1) * 8;
    int a_koff   = (q >> 1) * 8;
    int b_krow   = lr + (q & 1) * 8;
    int b_ncol0  = wn * 32 + (q >> 1) * 8;

    uint32_t abase = sb + SM_A;
    uint32_t bbase = sb + SM4_B;
#pragma unroll
    for (int ks = 0; ks < 8; ks++) {
        int k0 = ks * 16;
        uint32_t a0[4], a1[4];
        ldsm_x4(a0[0], a0[1], a0[2], a0[3],
                abase + (a_row_in) * SROW + (k0 + a_koff) * 2);
        ldsm_x4(a1[0], a1[1], a1[2], a1[3],
                abase + (a_row_in + 16) * SROW + (k0 + a_koff) * 2);
#pragma unroll
        for (int nt = 0; nt < 2; nt++) {
            uint32_t b[4];
            ldsm_x4_t(b[0], b[1], b[2], b[3],
                      bbase + (k0 + b_krow) * SROWB + (b_ncol0 + nt * 16) * 2);
            mma_f16(c[0][nt * 2 + 0], a0[0], a0[1], a0[2], a0[3], b[0], b[1]);
            mma_f16(c[0][nt * 2 + 1], a0[0], a0[1], a0[2], a0[3], b[2], b[3]);
            mma_f16(c[1][nt * 2 + 0], a1[0], a1[1], a1[2], a1[3], b[0], b[1]);
            mma_f16(c[1][nt * 2 + 1], a1[0], a1[1], a1[2], a1[3], b[2], b[3]);
        }
    }

    int trow = lane >> 2, tcol = (lane & 3) * 2;

#pragma unroll
    for (int mt = 0; mt < 2; mt++) {
        int rbase = r0 + wm * 32 + mt * 16 + trow;
#pragma unroll
        for (int nt = 0; nt < 4; nt++) {
            int col = wn * 32 + nt * 8 + tcol;
            if (col < 40) {
                if (rbase < n)
                    *(float2*)(C + (size_t)rbase * 40 + col) =
                        make_float2(c[mt][nt][0], c[mt][nt][1]);
                if (rbase + 8 < n)
                    *(float2*)(C + (size_t)(rbase + 8) * 40 + col) =
                        make_float2(c[mt][nt][2], c[mt][nt][3]);
            }
        }
    }

    float ap[4] = {0.f, 0.f, 0.f, 0.f}, dp[4] = {0.f, 0.f, 0.f, 0.f};
#pragma unroll
    for (int mt = 0; mt < 2; mt++)
#pragma unroll
        for (int nt = 0; nt < 4; nt++) {
            int col = wn * 32 + nt * 8 + tcol;
            if (col < 40) {
                float s0 = __ldg(asrc + col), s1 = __ldg(asrc + col + 1);
                float d0 = __ldg(adst + col), d1 = __ldg(adst + col + 1);
                ap[mt * 2 + 0] += c[mt][nt][0] * s0 + c[mt][nt][1] * s1;
                ap[mt * 2 + 1] += c[mt][nt][2] * s0 + c[mt][nt][3] * s1;
                dp[mt * 2 + 0] += c[mt][nt][0] * d0 + c[mt][nt][1] * d1;
                dp[mt * 2 + 1] += c[mt][nt][2] * d0 + c[mt][nt][3] * d1;
            }
        }
#pragma unroll
    for (int off = 1; off <= 2; off <<= 1)
#pragma unroll
        for (int v = 0; v < 4; v++) {
            ap[v] += __shfl_xor_sync(0xffffffffu, ap[v], off);
            dp[v] += __shfl_xor_sync(0xffffffffu, dp[v], off);
        }
    if ((lane & 3) == 0) {
#pragma unroll
        for (int mt = 0; mt < 2; mt++)
#pragma unroll
            for (int rr = 0; rr < 2; rr++) {
                int rl = wm * 32 + mt * 16 + trow + rr * 8;
                atomicAdd(&salS[rl], ap[mt * 2 + rr]);
                atomicAdd(&salD[rl], dp[mt * 2 + rr]);
            }
    }
    __syncthreads();
    if (tid < 128 && r0 + tid < n) {
        als[r0 + tid] = salS[tid];
        ald[r0 + tid] = salD[tid];
    }
}

__device__ __forceinline__ float leaky(float v) {
    return v > 0.f ? v : NEG_SLOPE * v;
}

// ===== fused softmax-aggregation, H=4 C=32: 2 edges/iter; chunked by node offset =====
__global__ __launch_bounds__(256) void fusedagg128_kernel(
    const int* __restrict__ rowptr, const int* __restrict__ csrsrc,
    const __half* __restrict__ h,
    const float* __restrict__ als, const float* __restrict__ ald,
    const float* __restrict__ bias,
    const float* __restrict__ bg, const float* __restrict__ bb,
    const float* __restrict__ bm, const float* __restrict__ bv,
    __half* __restrict__ feat, int noff, int ncnt)
{
    int d    = noff + ((blockIdx.x * blockDim.x + threadIdx.x) >> 5);
    int lane = threadIdx.x & 31;
    if (d >= noff + ncnt) return;
    int start = rowptr[d], end = rowptr[d + 1];
    int e    = lane >> 4;
    int c16  = lane & 15;
    int head = c16 >> 2;

    float aldh = __ldg(ald + (size_t)d * 4 + head);

    float acc[8];
#pragma unroll
    for (int i = 0; i < 8; i++) acc[i] = 0.f;
    float denom = 0.f;

    for (int p = start + e; p < end; p += 2) {
        int s = __ldg(csrsrc + p);
        float a = __ldg(als + (size_t)s * 4 + head);
        uint4 u = *(const uint4*)(h + (size_t)s * 128 + c16 * 8);
        float x = __expf(leaky(a + aldh));
        denom += x;
        float2 f0 = __half22float2(*(__half2*)&u.x);
        float2 f1 = __half22float2(*(__half2*)&u.y);
        float2 f2 = __half22float2(*(__half2*)&u.z);
        float2 f3 = __half22float2(*(__half2*)&u.w);
        acc[0] += x * f0.x; acc[1] += x * f0.y;
        acc[2] += x * f1.x; acc[3] += x * f1.y;
        acc[4] += x * f2.x; acc[5] += x * f2.y;
        acc[6] += x * f3.x; acc[7] += x * f3.y;
    }

    denom += __shfl_xor_sync(0xffffffffu, denom, 16);
#pragma unroll
    for (int i = 0; i < 8; i++)
        acc[i] += __shfl_xor_sync(0xffffffffu, acc[i], 16);

    if (e == 0) {
        float inv = 1.f / (denom + 1e-16f);
        int c = c16 * 8;
        float bi[8], gg[8], be[8], mm[8], vv[8];
        *(float4*)(bi)     = *(const float4*)(bias + c);
        *(float4*)(bi + 4) = *(const float4*)(bias + c + 4);
        *(float4*)(gg)     = *(const float4*)(bg + c);
        *(float4*)(gg + 4) = *(const float4*)(bg + c + 4);
        *(float4*)(be)     = *(const float4*)(bb + c);
        *(float4*)(be + 4) = *(const float4*)(bb + c + 4);
        *(float4*)(mm)     = *(const float4*)(bm + c);
        *(float4*)(mm + 4) = *(const float4*)(bm + c + 4);
        *(float4*)(vv)     = *(const float4*)(bv + c);
        *(float4*)(vv + 4) = *(const float4*)(bv + c + 4);
        __half h8[8];
#pragma unroll
        for (int i = 0; i < 8; i++) {
            float r = fmaxf(acc[i] * inv + bi[i], 0.f);
            r = (r - mm[i]) * rsqrtf(vv[i] + BN_EPS) * gg[i] + be[i];
            h8[i] = __float2half_rn(r);
        }
        *(uint4*)(feat + (size_t)d * 128 + c) = *(uint4*)h8;
    }
}

// ===== fused layer-3 aggregation (H=1, C=40, fp32 h): 2 edges/iter =====
__global__ __launch_bounds__(256) void fusedagg40_kernel(
    const int* __restrict__ rowptr, const int* __restrict__ csrsrc,
    const float* __restrict__ h,
    const float* __restrict__ als, const float* __restrict__ ald,
    const float* __restrict__ bias,
    float* __restrict__ out, int n)
{
    int d    = (blockIdx.x * blockDim.x + threadIdx.x) >> 5;
    int lane = threadIdx.x & 31;
    if (d >= n) return;
    int start = rowptr[d], end = rowptr[d + 1];
    int e   = lane >> 4;
    int c16 = lane & 15;
    bool act = c16 < 10;

    float aldd = __ldg(ald + d);

    float4 acc = make_float4(0.f, 0.f, 0.f, 0.f);
    float denom = 0.f;
    for (int p = start + e; p < end; p += 2) {
        int s = __ldg(csrsrc + p);
        float x = __expf(leaky(__ldg(als + s) + aldd));
        denom += x;
        if (act) {
            float4 h0 = *(const float4*)(h + (size_t)s * 40 + c16 * 4);
            acc.x += x * h0.x; acc.y += x * h0.y;
            acc.z += x * h0.z; acc.w += x * h0.w;
        }
    }

    denom += __shfl_xor_sync(0xffffffffu, denom, 16);
    acc.x += __shfl_xor_sync(0xffffffffu, acc.x, 16);
    acc.y += __shfl_xor_sync(0xffffffffu, acc.y, 16);
    acc.z += __shfl_xor_sync(0xffffffffu, acc.z, 16);
    acc.w += __shfl_xor_sync(0xffffffffu, acc.w, 16);

    bool writer = (e == 0) && act;
    float inv = 1.f / (denom + 1e-16f);
    float4 v = make_float4(-INFINITY, -INFINITY, -INFINITY, -INFINITY);
    if (writer) {
        float4 bi = *(const float4*)(bias + c16 * 4);
        v.x = acc.x * inv + bi.x;
        v.y = acc.y * inv + bi.y;
        v.z = acc.z * inv + bi.z;
        v.w = acc.w * inv + bi.w;
    }
    float lm = fmaxf(fmaxf(v.x, v.y), fmaxf(v.z, v.w));
#pragma unroll
    for (int o = 16; o > 0; o >>= 1)
        lm = fmaxf(lm, __shfl_xor_sync(0xffffffffu, lm, o));
    float ls = 0.f;
    if (writer)
        ls = __expf(v.x - lm) + __expf(v.y - lm) + __expf(v.z - lm) + __expf(v.w - lm);
#pragma unroll
    for (int o = 16; o > 0; o >>= 1)
        ls += __shfl_xor_sync(0xffffffffu, ls, o);
    float lse = lm + logf(ls);
    if (writer) {
        float4 r = make_float4(v.x - lse, v.y - lse, v.z - lse, v.w - lse);
        *(float4*)(out + (size_t)d * 40 + c16 * 4) = r;
    }
}

// =========================== host launch ===========================
extern "C" void kernel_launch(void* const* d_in, const int* in_sizes, int n_in,
                              void* d_out, int out_size)
{
    const float* x      = (const float*)d_in[0];
    const int*   ei     = (const int*)  d_in[1];
    const float* W1     = (const float*)d_in[2];
    const float* a_src1 = (const float*)d_in[3];
    const float* a_dst1 = (const float*)d_in[4];
    const float* b1     = (const float*)d_in[5];
    const float* W2     = (const float*)d_in[6];
    const float* a_src2 = (const float*)d_in[7];
    const float* a_dst2 = (const float*)d_in[8];
    const float* b2     = (const float*)d_in[9];
    const float* W3     = (const float*)d_in[10];
    const float* a_src3 = (const float*)d_in[11];
    const float* a_dst3 = (const float*)d_in[12];
    const float* b3     = (const float*)d_in[13];
    const float* bn1_g  = (const float*)d_in[14];
    const float* bn1_b  = (const float*)d_in[15];
    const float* bn1_m  = (const float*)d_in[16];
    const float* bn1_v  = (const float*)d_in[17];
    const float* bn2_g  = (const float*)d_in[18];
    const float* bn2_b  = (const float*)d_in[19];
    const float* bn2_m  = (const float*)d_in[20];
    const float* bn2_v  = (const float*)d_in[21];
    float* out = (float*)d_out;

    int n    = in_sizes[0] / 128;   // 50000
    int E0   = in_sizes[1] / 2;     // 800000
    int Etot = E0 + n;

    float *p_hp, *p_als, *p_ald;
    __half *p_hph, *p_feat;
    int *p_deg, *p_rank, *p_incl, *p_bsum, *p_rowptr, *p_csrsrc;
    cudaGetSymbolAddress((void**)&p_hp,     g_hp);
    cudaGetSymbolAddress((void**)&p_hph,    g_hph);
    cudaGetSymbolAddress((void**)&p_als,    g_al_src);
    cudaGetSymbolAddress((void**)&p_ald,    g_al_dst);
    cudaGetSymbolAddress((void**)&p_feat,   g_feat);
    cudaGetSymbolAddress((void**)&p_deg,    g_deg);
    cudaGetSymbolAddress((void**)&p_rank,   g_rank);
    cudaGetSymbolAddress((void**)&p_incl,   g_incl);
    cudaGetSymbolAddress((void**)&p_bsum,   g_bsum);
    cudaGetSymbolAddress((void**)&p_rowptr, g_rowptr);
    cudaGetSymbolAddress((void**)&p_csrsrc, g_csrsrc);

    cudaFuncSetAttribute(mma_gemm128_kernel<true>,
                         cudaFuncAttributeMaxDynamicSharedMemorySize, SM_TOT);
    cudaFuncSetAttribute(mma_gemm128_kernel<false>,
                         cudaFuncAttributeMaxDynamicSharedMemorySize, SM_TOT);
    cudaFuncSetAttribute(mma_gemm40_kernel,
                         cudaFuncAttributeMaxDynamicSharedMemorySize, SM4_TOT);

    static cudaStream_t s2 = nullptr;
    static cudaEvent_t evA = nullptr, evB = nullptr, evG1 = nullptr;
    static cudaEvent_t evG2c0 = nullptr, evG2c1 = nullptr, ev40c1 = nullptr;
    if (s2 == nullptr) {
        cudaStreamCreateWithFlags(&s2, cudaStreamNonBlocking);
        cudaEventCreateWithFlags(&evA, cudaEventDisableTiming);
        cudaEventCreateWithFlags(&evB, cudaEventDisableTiming);
        cudaEventCreateWithFlags(&evG1, cudaEventDisableTiming);
        cudaEventCreateWithFlags(&evG2c0, cudaEventDisableTiming);
        cudaEventCreateWithFlags(&evG2c1, cudaEventDisableTiming);
        cudaEventCreateWithFlags(&ev40c1, cudaEventDisableTiming);
    }

    const int T = 256;
    int edgeBlocks = (Etot + T - 1) / T;
    int scanBlocks = (n + 1023) / 1024;
    int nodeBlocks = (n + T - 1) / T;
    int mmaBlocks  = (n + 127) / 128;
    int warpNodeBlocks = (n * 32 + T - 1) / T;

    int half = ((n / 2 + 127) / 128) * 128;   // 25088
    int c1   = n - half;
    int gB0  = half / 128;
    int gB1  = (c1 + 127) / 128;
    int aB0  = (half * 32 + T - 1) / T;
    int aB1  = (c1 * 32 + T - 1) / T;

    // ---- fork: CSR build on s2, concurrent with layer-1 GEMM ----
    cudaEventRecord(evA, 0);
    cudaStreamWaitEvent(s2, evA, 0);

    cudaMemsetAsync(p_deg, 0, n * sizeof(int), s2);
    hist_kernel<<<edgeBlocks, T, 0, s2>>>(ei, E0, n, p_deg, p_rank);
    scan1_kernel<<<scanBlocks, 1024, 0, s2>>>(p_deg, p_incl, p_bsum, n);
    scan3_kernel<<<nodeBlocks, T, 0, s2>>>(p_incl, p_bsum, p_rowptr, n, scanBlocks);
    scatter_kernel<<<edgeBlocks, T, 0, s2>>>(ei, E0, n, p_rowptr, p_rank, p_csrsrc);

    // ---------------- layer 1 GEMM (full, on s0) ----------------
    mma_gemm128_kernel<true><<<mmaBlocks, T, SM_TOT>>>(
        x, nullptr, W1, a_src1, a_dst1, p_hph, p_als, p_ald, 0, n);
    cudaEventRecord(evG1, 0);
    cudaEventRecord(evB, s2);

    // ---------------- pipelined layers: chunk0 on s0, chunk1 on s2 ----------------
    cudaStreamWaitEvent(0, evB, 0);
    cudaStreamWaitEvent(s2, evG1, 0);
    fusedagg128_kernel<<<aB0, T>>>(p_rowptr, p_csrsrc, p_hph, p_als, p_ald,
                                   b1, bn1_g, bn1_b, bn1_m, bn1_v,
                                   p_feat, 0, half);
    fusedagg128_kernel<<<aB1, T, 0, s2>>>(p_rowptr, p_csrsrc, p_hph, p_als, p_ald,
                                          b1, bn1_g, bn1_b, bn1_m, bn1_v,
                                          p_feat, half, c1);
    mma_gemm128_kernel<false><<<gB0, T, SM_TOT>>>(
        nullptr, p_feat, W2, a_src2, a_dst2, p_hph, p_als, p_ald, 0, n);
    cudaEventRecord(evG2c0, 0);
    mma_gemm128_kernel<false><<<gB1, T, SM_TOT, s2>>>(
        nullptr, p_feat, W2, a_src2, a_dst2, p_hph, p_als, p_ald, half, n);
    cudaEventRecord(evG2c1, s2);

    cudaStreamWaitEvent(0, evG2c1, 0);
    cudaStreamWaitEvent(s2, evG2c0, 0);
    fusedagg128_kernel<<<aB0, T>>>(p_rowptr, p_csrsrc, p_hph, p_als, p_ald,
                                   b2, bn2_g, bn2_b, bn2_m, bn2_v,
                                   p_feat, 0, half);
    fusedagg128_kernel<<<aB1, T, 0, s2>>>(p_rowptr, p_csrsrc, p_hph, p_als, p_ald,
                                          b2, bn2_g, bn2_b, bn2_m, bn2_v,
                                          p_feat, half, c1);
    mma_gemm40_kernel<<<gB0, T, SM4_TOT>>>(p_feat, W3, a_src3, a_dst3,
                                           p_hp, p_als, p_ald, 0, n);
    mma_gemm40_kernel<<<gB1, T, SM4_TOT, s2>>>(p_feat, W3, a_src3, a_dst3,
                                               p_hp, p_als, p_ald, half, n);
    cudaEventRecord(ev40c1, s2);

    cudaStreamWaitEvent(0, ev40c1, 0);
    fusedagg40_kernel<<<warpNodeBlocks, T>>>(p_rowptr, p_csrsrc, p_hp, p_als, p_ald,
                                             b3, out, n);
}

// round 14
// speedup vs baseline: 1.3603x; 1.0235x over previous
#include <cuda_runtime.h>
#include <cuda_bf16.h>
#include <cuda_fp16.h>
#include <math.h>
#include <stdint.h>

#define NN    50000
#define EE    800000
#define ETOT  (EE + NN)
#define NEG_SLOPE 0.2f
#define BN_EPS    1e-5f

// ---------------- scratch (device globals; no allocation) ----------------
__device__ __half g_hp3[(size_t)NN * 40];      // layer-3 h (fp16)
__device__ __half g_hph[(size_t)NN * 128];     // layers 1/2 h (fp16, agg input)
__device__ __half g_feat[(size_t)NN * 128];    // feat (fp16, GEMM input)
__device__ float g_al_src[NN * 4];
__device__ float g_al_dst[NN * 4];
__device__ int   g_deg[NN];
__device__ int   g_rank[ETOT];
__device__ int   g_incl[NN + 1024];
__device__ int   g_bsum[64];
__device__ int   g_rowptr[NN + 1];
__device__ int   g_csrsrc[ETOT];

__device__ __forceinline__ uint32_t smem_u32(const void* p) {
    uint32_t a;
    asm("{ .reg .u64 t; cvta.to.shared.u64 t, %1; cvt.u32.u64 %0, t; }" : "=r"(a) : "l"(p));
    return a;
}

// =========================== CSR build (rank-based; x4 vectorized) ===========================
// E0 assumed multiple of 4 (800000). Threads [0, E0/4) handle 4 real edges each;
// threads [E0/4, E0/4 + n) handle one self-loop each.
__global__ void hist_kernel(const int* __restrict__ ei, int E0, int n,
                            int* __restrict__ deg, int* __restrict__ rank)
{
    int t = blockIdx.x * blockDim.x + threadIdx.x;
    int q = E0 >> 2;
    if (t < q) {
        int4 d4 = *(const int4*)(ei + E0 + t * 4);
        int4 r4;
        r4.x = atomicAdd(&deg[d4.x], 1);
        r4.y = atomicAdd(&deg[d4.y], 1);
        r4.z = atomicAdd(&deg[d4.z], 1);
        r4.w = atomicAdd(&deg[d4.w], 1);
        *(int4*)(rank + t * 4) = r4;
    } else if (t < q + n) {
        int d = t - q;
        rank[E0 + d] = atomicAdd(&deg[d], 1);
    }
}

__global__ void scan1_kernel(const int* __restrict__ deg, int* __restrict__ incl,
                             int* __restrict__ bsum, int n)
{
    __shared__ int wsum[32];
    int tid = threadIdx.x;
    int i = blockIdx.x * 1024 + tid;
    int lane = tid & 31, wid = tid >> 5;
    int s = (i < n) ? deg[i] : 0;
#pragma unroll
    for (int o = 1; o < 32; o <<= 1) {
        int t = __shfl_up_sync(0xffffffffu, s, o);
        if (lane >= o) s += t;
    }
    if (lane == 31) wsum[wid] = s;
    __syncthreads();
    if (wid == 0) {
        int w = wsum[lane];
#pragma unroll
        for (int o = 1; o < 32; o <<= 1) {
            int t = __shfl_up_sync(0xffffffffu, w, o);
            if (lane >= o) w += t;
        }
        wsum[lane] = w;
    }
    __syncthreads();
    int v = s + ((wid > 0) ? wsum[wid - 1] : 0);
    incl[i] = v;
    if (tid == 1023) bsum[blockIdx.x] = v;
}

__global__ void scan3_kernel(const int* __restrict__ incl, const int* __restrict__ bsum,
                             int* __restrict__ rowptr, int n, int nb)
{
    __shared__ int pref[64];
    if (threadIdx.x == 0) {
        int acc = 0;
        for (int b = 0; b < nb; b++) { pref[b] = acc; acc += bsum[b]; }
    }
    __syncthreads();
    int i = blockIdx.x * blockDim.x + threadIdx.x;
    if (i < n) rowptr[i + 1] = incl[i] + pref[i >> 10];
    if (i == 0) rowptr[0] = 0;
}

__global__ void scatter_kernel(const int* __restrict__ ei, int E0, int n,
                               const int* __restrict__ rowptr,
                               const int* __restrict__ rank,
                               int* __restrict__ csrsrc)
{
    int t = blockIdx.x * blockDim.x + threadIdx.x;
    int q = E0 >> 2;
    if (t < q) {
        int4 s4 = *(const int4*)(ei + t * 4);
        int4 d4 = *(const int4*)(ei + E0 + t * 4);
        int4 r4 = *(const int4*)(rank + t * 4);
        int p0 = __ldg(rowptr + d4.x) + r4.x;
        int p1 = __ldg(rowptr + d4.y) + r4.y;
        int p2 = __ldg(rowptr + d4.z) + r4.z;
        int p3 = __ldg(rowptr + d4.w) + r4.w;
        csrsrc[p0] = s4.x;
        csrsrc[p1] = s4.y;
        csrsrc[p2] = s4.z;
        csrsrc[p3] = s4.w;
    } else if (t < q + n) {
        int d = t - q;
        csrsrc[__ldg(rowptr + d) + rank[E0 + d]] = d;
    }
}

// =========================== HMMA common (single fp16) ===========================
#define SROW    272
#define SM_A    0
#define SM_B    34816
#define SM_TOT  69632

#define SROWB   144
#define SM4_B   34816
#define SM4_SAL 53248
#define SM4_TOT 54272

__device__ __forceinline__ void ldsm_x4(uint32_t& r0, uint32_t& r1, uint32_t& r2,
                                        uint32_t& r3, uint32_t addr) {
    asm volatile("ldmatrix.sync.aligned.m8n8.x4.shared.b16 {%0,%1,%2,%3}, [%4];"
                 : "=r"(r0), "=r"(r1), "=r"(r2), "=r"(r3) : "r"(addr));
}
__device__ __forceinline__ void ldsm_x4_t(uint32_t& r0, uint32_t& r1, uint32_t& r2,
                                          uint32_t& r3, uint32_t addr) {
    asm volatile("ldmatrix.sync.aligned.m8n8.x4.trans.shared.b16 {%0,%1,%2,%3}, [%4];"
                 : "=r"(r0), "=r"(r1), "=r"(r2), "=r"(r3) : "r"(addr));
}
__device__ __forceinline__ void mma_f16(float* c, uint32_t a0, uint32_t a1, uint32_t a2,
                                        uint32_t a3, uint32_t b0, uint32_t b1) {
    asm volatile("mma.sync.aligned.m16n8k16.row.col.f32.f16.f16.f32 "
                 "{%0,%1,%2,%3}, {%4,%5,%6,%7}, {%8,%9}, {%0,%1,%2,%3};"
                 : "+f"(c[0]), "+f"(c[1]), "+f"(c[2]), "+f"(c[3])
                 : "r"(a0), "r"(a1), "r"(a2), "r"(a3), "r"(b0), "r"(b1));
}

// ===== wide GEMM 128x128 (A fp16, B fp16) + fused al dots; D fp16; chunked by r0off =====
template<bool A32>
__global__ __launch_bounds__(256, 2) void mma_gemm128_kernel(
    const float* __restrict__ Af,
    const __half* __restrict__ Ah,
    const float* __restrict__ W,
    const float* __restrict__ asrc, const float* __restrict__ adst,
    __half* __restrict__ hph, float* __restrict__ als, float* __restrict__ ald,
    int r0off, int n)
{
    extern __shared__ char smem[];
    int tid = threadIdx.x, wid = tid >> 5, lane = tid & 31;
    int r0 = r0off + blockIdx.x * 128;

    for (int i = tid; i < 2048; i += 256) {
        int row = i >> 4, ch = i & 15;
        uint4 vh;
        if (A32) {
            float f[8];
            if (r0 + row < n) {
                *(float4*)(f)     = *(const float4*)(Af + (size_t)(r0 + row) * 128 + ch * 8);
                *(float4*)(f + 4) = *(const float4*)(Af + (size_t)(r0 + row) * 128 + ch * 8 + 4);
            } else {
#pragma unroll
                for (int q = 0; q < 8; q++) f[q] = 0.f;
            }
            __half h8[8];
#pragma unroll
            for (int q = 0; q < 8; q++) h8[q] = __float2half_rn(f[q]);
            vh = *(uint4*)h8;
        } else {
            vh = (r0 + row < n) ? *(const uint4*)(Ah + (size_t)(r0 + row) * 128 + ch * 8)
                                : make_uint4(0u, 0u, 0u, 0u);
        }
        *(uint4*)(smem + SM_A + row * SROW + ch * 16) = vh;
    }
    for (int i = tid; i < 2048; i += 256) {
        int row = i >> 4, ch = i & 15;
        float f[8];
        *(float4*)(f)     = *(const float4*)(W + (size_t)row * 128 + ch * 8);
        *(float4*)(f + 4) = *(const float4*)(W + (size_t)row * 128 + ch * 8 + 4);
        __half h8[8];
#pragma unroll
        for (int q = 0; q < 8; q++) h8[q] = __float2half_rn(f[q]);
        *(uint4*)(smem + SM_B + row * SROW + ch * 16) = *(uint4*)h8;
    }
    __syncthreads();

    int wm = wid & 3;
    int wn = wid >> 2;
    uint32_t sb = smem_u32(smem);

    float c[2][8][4];
#pragma unroll
    for (int mt = 0; mt < 2; mt++)
#pragma unroll
        for (int nt = 0; nt < 8; nt++)
#pragma unroll
            for (int q = 0; q < 4; q++) c[mt][nt][q] = 0.f;

    int q  = lane >> 3;
    int lr = lane & 7;
    int a_row_in = wm * 32 + lr + (q & 1) * 8;
    int a_koff   = (q >> 1) * 8;
    int b_krow   = lr + (q & 1) * 8;
    int b_ncol0  = wn * 64 + (q >> 1) * 8;

    uint32_t abase = sb + SM_A;
    uint32_t bbase = sb + SM_B;
#pragma unroll
    for (int ks = 0; ks < 8; ks++) {
        int k0 = ks * 16;
        uint32_t a0[4], a1[4];
        ldsm_x4(a0[0], a0[1], a0[2], a0[3],
                abase + (a_row_in) * SROW + (k0 + a_koff) * 2);
        ldsm_x4(a1[0], a1[1], a1[2], a1[3],
                abase + (a_row_in + 16) * SROW + (k0 + a_koff) * 2);
#pragma unroll
        for (int nt = 0; nt < 4; nt++) {
            uint32_t b[4];
            ldsm_x4_t(b[0], b[1], b[2], b[3],
                      bbase + (k0 + b_krow) * SROW + (b_ncol0 + nt * 16) * 2);
            mma_f16(c[0][nt * 2 + 0], a0[0], a0[1], a0[2], a0[3], b[0], b[1]);
            mma_f16(c[0][nt * 2 + 1], a0[0], a0[1], a0[2], a0[3], b[2], b[3]);
            mma_f16(c[1][nt * 2 + 0], a1[0], a1[1], a1[2], a1[3], b[0], b[1]);
            mma_f16(c[1][nt * 2 + 1], a1[0], a1[1], a1[2], a1[3], b[2], b[3]);
        }
    }

    int trow = lane >> 2, tcol = (lane & 3) * 2;

#pragma unroll
    for (int mt = 0; mt < 2; mt++) {
        int rbase = r0 + wm * 32 + mt * 16 + trow;
#pragma unroll
        for (int nt = 0; nt < 8; nt++) {
            int col = wn * 64 + nt * 8 + tcol;
            if (rbase < n)
                *(__half2*)(hph + (size_t)rbase * 128 + col) =
                    __floats2half2_rn(c[mt][nt][0], c[mt][nt][1]);
            if (rbase + 8 < n)
                *(__half2*)(hph + (size_t)(rbase + 8) * 128 + col) =
                    __floats2half2_rn(c[mt][nt][2], c[mt][nt][3]);
        }
    }

    float ap[2][4], dp[2][4];
#pragma unroll
    for (int hh = 0; hh < 2; hh++)
#pragma unroll
        for (int v = 0; v < 4; v++) { ap[hh][v] = 0.f; dp[hh][v] = 0.f; }
#pragma unroll
    for (int nt = 0; nt < 8; nt++) {
        int col = wn * 64 + nt * 8 + tcol;
        int hh = nt >> 2;
        float s0 = __ldg(asrc + col), s1 = __ldg(asrc + col + 1);
        float d0 = __ldg(adst + col), d1 = __ldg(adst + col + 1);
#pragma unroll
        for (int mt = 0; mt < 2; mt++) {
            ap[hh][mt * 2 + 0] += c[mt][nt][0] * s0 + c[mt][nt][1] * s1;
            ap[hh][mt * 2 + 1] += c[mt][nt][2] * s0 + c[mt][nt][3] * s1;
            dp[hh][mt * 2 + 0] += c[mt][nt][0] * d0 + c[mt][nt][1] * d1;
            dp[hh][mt * 2 + 1] += c[mt][nt][2] * d0 + c[mt][nt][3] * d1;
        }
    }
#pragma unroll
    for (int off = 1; off <= 2; off <<= 1)
#pragma unroll
        for (int hh = 0; hh < 2; hh++)
#pragma unroll
            for (int v = 0; v < 4; v++) {
                ap[hh][v] += __shfl_xor_sync(0xffffffffu, ap[hh][v], off);
                dp[hh][v] += __shfl_xor_sync(0xffffffffu, dp[hh][v], off);
            }
    if ((lane & 3) == 0) {
#pragma unroll
        for (int mt = 0; mt < 2; mt++)
#pragma unroll
            for (int rr = 0; rr < 2; rr++) {
                int row = r0 + wm * 32 + mt * 16 + trow + rr * 8;
                int v = mt * 2 + rr;
                if (row < n) {
                    als[row * 4 + wn * 2 + 0] = ap[0][v];
                    als[row * 4 + wn * 2 + 1] = ap[1][v];
                    ald[row * 4 + wn * 2 + 0] = dp[0][v];
                    ald[row * 4 + wn * 2 + 1] = dp[1][v];
                }
            }
    }
}

// ===== layer-3 GEMM: [n,128] @ [128,40] (A fp16, B fp16, N padded 64); C fp16; chunked =====
__global__ __launch_bounds__(256, 2) void mma_gemm40_kernel(
    const __half* __restrict__ Ah,
    const float* __restrict__ W,
    const float* __restrict__ asrc, const float* __restrict__ adst,
    __half* __restrict__ C, float* __restrict__ als, float* __restrict__ ald,
    int r0off, int n)
{
    extern __shared__ char smem[];
    float* salS = (float*)(smem + SM4_SAL);
    float* salD = salS + 128;
    int tid = threadIdx.x, wid = tid >> 5, lane = tid & 31;
    int r0 = r0off + blockIdx.x * 128;

    for (int i = tid; i < 2048; i += 256) {
        int row = i >> 4, ch = i & 15;
        uint4 vh = (r0 + row < n) ? *(const uint4*)(Ah + (size_t)(r0 + row) * 128 + ch * 8)
                                  : make_uint4(0u, 0u, 0u, 0u);
        *(uint4*)(smem + SM_A + row * SROW + ch * 16) = vh;
    }
    for (int i = tid; i < 8192; i += 256) {
        int row = i >> 6, cc = i & 63;
        float f = (cc < 40) ? W[(size_t)row * 40 + cc] : 0.f;
        *(__half*)(smem + SM4_B + row * SROWB + cc * 2) = __float2half_rn(f);
    }
    if (tid < 128) { salS[tid] = 0.f; salD[tid] = 0.f; }
    __syncthreads();

    int wm = wid & 3;
    int wn = wid >> 2;
    uint32_t sb = smem_u32(smem);

    float c[2][4][4];
#pragma unroll
    for (int mt = 0; mt < 2; mt++)
#pragma unroll
        for (int nt = 0; nt < 4; nt++)
#pragma unroll
            for (int q = 0; q < 4; q++) c[mt][nt][q] = 0.f;

    int q  = lane >> 3;
    int lr = lane & 7;
    int a_row_in = wm * 32 + lr + (q & 1) * 8;
    int a_koff   = (q >> 1) * 8;
    int b_krow   = lr + (q & 1) * 8;
    int b_ncol0  = wn * 32 + (q >> 1) * 8;

    uint32_t abase = sb + SM_A;
    uint32_t bbase = sb + SM4_B;
#pragma unroll
    for (int ks = 0; ks < 8; ks++) {
        int k0 = ks * 16;
        uint32_t a0[4], a1[4];
        ldsm_x4(a0[0], a0[1], a0[2], a0[3],
                abase + (a_row_in) * SROW + (k0 + a_koff) * 2);
        ldsm_x4(a1[0], a1[1], a1[2], a1[3],
                abase + (a_row_in + 16) * SROW + (k0 + a_koff) * 2);
#pragma unroll
        for (int nt = 0; nt < 2; nt++) {
            uint32_t b[4];
            ldsm_x4_t(b[0], b[1], b[2], b[3],
                      bbase + (k0 + b_krow) * SROWB + (b_ncol0 + nt * 16) * 2);
            mma_f16(c[0][nt * 2 + 0], a0[0], a0[1], a0[2], a0[3], b[0], b[1]);
            mma_f16(c[0][nt * 2 + 1], a0[0], a0[1], a0[2], a0[3], b[2], b[3]);
            mma_f16(c[1][nt * 2 + 0], a1[0], a1[1], a1[2], a1[3], b[0], b[1]);
            mma_f16(c[1][nt * 2 + 1], a1[0], a1[1], a1[2], a1[3], b[2], b[3]);
        }
    }

    int trow = lane >> 2, tcol = (lane & 3) * 2;

#pragma unroll
    for (int mt = 0; mt < 2; mt++) {
        int rbase = r0 + wm * 32 + mt * 16 + trow;
#pragma unroll
        for (int nt = 0; nt < 4; nt++) {
            int col = wn * 32 + nt * 8 + tcol;
            if (col < 40) {
                if (rbase < n)
                    *(__half2*)(C + (size_t)rbase * 40 + col) =
                        __floats2half2_rn(c[mt][nt][0], c[mt][nt][1]);
                if (rbase + 8 < n)
                    *(__half2*)(C + (size_t)(rbase + 8) * 40 + col) =
                        __floats2half2_rn(c[mt][nt][2], c[mt][nt][3]);
            }
        }
    }

    float ap[4] = {0.f, 0.f, 0.f, 0.f}, dp[4] = {0.f, 0.f, 0.f, 0.f};
#pragma unroll
    for (int mt = 0; mt < 2; mt++)
#pragma unroll
        for (int nt = 0; nt < 4; nt++) {
            int col = wn * 32 + nt * 8 + tcol;
            if (col < 40) {
                float s0 = __ldg(asrc + col), s1 = __ldg(asrc + col + 1);
                float d0 = __ldg(adst + col), d1 = __ldg(adst + col + 1);
                ap[mt * 2 + 0] += c[mt][nt][0] * s0 + c[mt][nt][1] * s1;
                ap[mt * 2 + 1] += c[mt][nt][2] * s0 + c[mt][nt][3] * s1;
                dp[mt * 2 + 0] += c[mt][nt][0] * d0 + c[mt][nt][1] * d1;
                dp[mt * 2 + 1] += c[mt][nt][2] * d0 + c[mt][nt][3] * d1;
            }
        }
#pragma unroll
    for (int off = 1; off <= 2; off <<= 1)
#pragma unroll
        for (int v = 0; v < 4; v++) {
            ap[v] += __shfl_xor_sync(0xffffffffu, ap[v], off);
            dp[v] += __shfl_xor_sync(0xffffffffu, dp[v], off);
        }
    if ((lane & 3) == 0) {
#pragma unroll
        for (int mt = 0; mt < 2; mt++)
#pragma unroll
            for (int rr = 0; rr < 2; rr++) {
                int rl = wm * 32 + mt * 16 + trow + rr * 8;
                atomicAdd(&salS[rl], ap[mt * 2 + rr]);
                atomicAdd(&salD[rl], dp[mt * 2 + rr]);
            }
    }
    __syncthreads();
    if (tid < 128 && r0 + tid < n) {
        als[r0 + tid] = salS[tid];
        ald[r0 + tid] = salD[tid];
    }
}

__device__ __forceinline__ float leaky(float v) {
    return v > 0.f ? v : NEG_SLOPE * v;
}

// ===== fused softmax-aggregation, H=4 C=32: 2 edges/iter; chunked by node offset =====
__global__ __launch_bounds__(256) void fusedagg128_kernel(
    const int* __restrict__ rowptr, const int* __restrict__ csrsrc,
    const __half* __restrict__ h,
    const float* __restrict__ als, const float* __restrict__ ald,
    const float* __restrict__ bias,
    const float* __restrict__ bg, const float* __restrict__ bb,
    const float* __restrict__ bm, const float* __restrict__ bv,
    __half* __restrict__ feat, int noff, int ncnt)
{
    int d    = noff + ((blockIdx.x * blockDim.x + threadIdx.x) >> 5);
    int lane = threadIdx.x & 31;
    if (d >= noff + ncnt) return;
    int start = rowptr[d], end = rowptr[d + 1];
    int e    = lane >> 4;
    int c16  = lane & 15;
    int head = c16 >> 2;

    float aldh = __ldg(ald + (size_t)d * 4 + head);

    float acc[8];
#pragma unroll
    for (int i = 0; i < 8; i++) acc[i] = 0.f;
    float denom = 0.f;

    for (int p = start + e; p < end; p += 2) {
        int s = __ldg(csrsrc + p);
        float a = __ldg(als + (size_t)s * 4 + head);
        uint4 u = *(const uint4*)(h + (size_t)s * 128 + c16 * 8);
        float x = __expf(leaky(a + aldh));
        denom += x;
        float2 f0 = __half22float2(*(__half2*)&u.x);
        float2 f1 = __half22float2(*(__half2*)&u.y);
        float2 f2 = __half22float2(*(__half2*)&u.z);
        float2 f3 = __half22float2(*(__half2*)&u.w);
        acc[0] += x * f0.x; acc[1] += x * f0.y;
        acc[2] += x * f1.x; acc[3] += x * f1.y;
        acc[4] += x * f2.x; acc[5] += x * f2.y;
        acc[6] += x * f3.x; acc[7] += x * f3.y;
    }

    denom += __shfl_xor_sync(0xffffffffu, denom, 16);
#pragma unroll
    for (int i = 0; i < 8; i++)
        acc[i] += __shfl_xor_sync(0xffffffffu, acc[i], 16);

    if (e == 0) {
        float inv = 1.f / (denom + 1e-16f);
        int c = c16 * 8;
        float bi[8], gg[8], be[8], mm[8], vv[8];
        *(float4*)(bi)     = *(const float4*)(bias + c);
        *(float4*)(bi + 4) = *(const float4*)(bias + c + 4);
        *(float4*)(gg)     = *(const float4*)(bg + c);
        *(float4*)(gg + 4) = *(const float4*)(bg + c + 4);
        *(float4*)(be)     = *(const float4*)(bb + c);
        *(float4*)(be + 4) = *(const float4*)(bb + c + 4);
        *(float4*)(mm)     = *(const float4*)(bm + c);
        *(float4*)(mm + 4) = *(const float4*)(bm + c + 4);
        *(float4*)(vv)     = *(const float4*)(bv + c);
        *(float4*)(vv + 4) = *(const float4*)(bv + c + 4);
        __half h8[8];
#pragma unroll
        for (int i = 0; i < 8; i++) {
            float r = fmaxf(acc[i] * inv + bi[i], 0.f);
            r = (r - mm[i]) * rsqrtf(vv[i] + BN_EPS) * gg[i] + be[i];
            h8[i] = __float2half_rn(r);
        }
        *(uint4*)(feat + (size_t)d * 128 + c) = *(uint4*)h8;
    }
}

// ===== fused layer-3 aggregation (H=1, C=40, fp16 h): 2 edges/iter =====
__global__ __launch_bounds__(256) void fusedagg40_kernel(
    const int* __restrict__ rowptr, const int* __restrict__ csrsrc,
    const __half* __restrict__ h,
    const float* __restrict__ als, const float* __restrict__ ald,
    const float* __restrict__ bias,
    float* __restrict__ out, int n)
{
    int d    = (blockIdx.x * blockDim.x + threadIdx.x) >> 5;
    int lane = threadIdx.x & 31;
    if (d >= n) return;
    int start = rowptr[d], end = rowptr[d + 1];
    int e   = lane >> 4;
    int c16 = lane & 15;
    bool act = c16 < 10;

    float aldd = __ldg(ald + d);

    float4 acc = make_float4(0.f, 0.f, 0.f, 0.f);
    float denom = 0.f;
    for (int p = start + e; p < end; p += 2) {
        int s = __ldg(csrsrc + p);
        float x = __expf(leaky(__ldg(als + s) + aldd));
        denom += x;
        if (act) {
            uint2 u = *(const uint2*)(h + (size_t)s * 40 + c16 * 4);
            float2 f0 = __half22float2(*(__half2*)&u.x);
            float2 f1 = __half22float2(*(__half2*)&u.y);
            acc.x += x * f0.x; acc.y += x * f0.y;
            acc.z += x * f1.x; acc.w += x * f1.y;
        }
    }

    denom += __shfl_xor_sync(0xffffffffu, denom, 16);
    acc.x += __shfl_xor_sync(0xffffffffu, acc.x, 16);
    acc.y += __shfl_xor_sync(0xffffffffu, acc.y, 16);
    acc.z += __shfl_xor_sync(0xffffffffu, acc.z, 16);
    acc.w += __shfl_xor_sync(0xffffffffu, acc.w, 16);

    bool writer = (e == 0) && act;
    float inv = 1.f / (denom + 1e-16f);
    float4 v = make_float4(-INFINITY, -INFINITY, -INFINITY, -INFINITY);
    if (writer) {
        float4 bi = *(const float4*)(bias + c16 * 4);
        v.x = acc.x * inv + bi.x;
        v.y = acc.y * inv + bi.y;
        v.z = acc.z * inv + bi.z;
        v.w = acc.w * inv + bi.w;
    }
    float lm = fmaxf(fmaxf(v.x, v.y), fmaxf(v.z, v.w));
#pragma unroll
    for (int o = 16; o > 0; o >>= 1)
        lm = fmaxf(lm, __shfl_xor_sync(0xffffffffu, lm, o));
    float ls = 0.f;
    if (writer)
        ls = __expf(v.x - lm) + __expf(v.y - lm) + __expf(v.z - lm) + __expf(v.w - lm);
#pragma unroll
    for (int o = 16; o > 0; o >>= 1)
        ls += __shfl_xor_sync(0xffffffffu, ls, o);
    float lse = lm + logf(ls);
    if (writer) {
        float4 r = make_float4(v.x - lse, v.y - lse, v.z - lse, v.w - lse);
        *(float4*)(out + (size_t)d * 40 + c16 * 4) = r;
    }
}

// =========================== host launch ===========================
extern "C" void kernel_launch(void* const* d_in, const int* in_sizes, int n_in,
                              void* d_out, int out_size)
{
    const float* x      = (const float*)d_in[0];
    const int*   ei     = (const int*)  d_in[1];
    const float* W1     = (const float*)d_in[2];
    const float* a_src1 = (const float*)d_in[3];
    const float* a_dst1 = (const float*)d_in[4];
    const float* b1     = (const float*)d_in[5];
    const float* W2     = (const float*)d_in[6];
    const float* a_src2 = (const float*)d_in[7];
    const float* a_dst2 = (const float*)d_in[8];
    const float* b2     = (const float*)d_in[9];
    const float* W3     = (const float*)d_in[10];
    const float* a_src3 = (const float*)d_in[11];
    const float* a_dst3 = (const float*)d_in[12];
    const float* b3     = (const float*)d_in[13];
    const float* bn1_g  = (const float*)d_in[14];
    const float* bn1_b  = (const float*)d_in[15];
    const float* bn1_m  = (const float*)d_in[16];
    const float* bn1_v  = (const float*)d_in[17];
    const float* bn2_g  = (const float*)d_in[18];
    const float* bn2_b  = (const float*)d_in[19];
    const float* bn2_m  = (const float*)d_in[20];
    const float* bn2_v  = (const float*)d_in[21];
    float* out = (float*)d_out;

    int n    = in_sizes[0] / 128;   // 50000
    int E0   = in_sizes[1] / 2;     // 800000
    int Etot = E0 + n;

    float *p_als, *p_ald;
    __half *p_hp3, *p_hph, *p_feat;
    int *p_deg, *p_rank, *p_incl, *p_bsum, *p_rowptr, *p_csrsrc;
    cudaGetSymbolAddress((void**)&p_hp3,    g_hp3);
    cudaGetSymbolAddress((void**)&p_hph,    g_hph);
    cudaGetSymbolAddress((void**)&p_als,    g_al_src);
    cudaGetSymbolAddress((void**)&p_ald,    g_al_dst);
    cudaGetSymbolAddress((void**)&p_feat,   g_feat);
    cudaGetSymbolAddress((void**)&p_deg,    g_deg);
    cudaGetSymbolAddress((void**)&p_rank,   g_rank);
    cudaGetSymbolAddress((void**)&p_incl,   g_incl);
    cudaGetSymbolAddress((void**)&p_bsum,   g_bsum);
    cudaGetSymbolAddress((void**)&p_rowptr, g_rowptr);
    cudaGetSymbolAddress((void**)&p_csrsrc, g_csrsrc);

    cudaFuncSetAttribute(mma_gemm128_kernel<true>,
                         cudaFuncAttributeMaxDynamicSharedMemorySize, SM_TOT);
    cudaFuncSetAttribute(mma_gemm128_kernel<false>,
                         cudaFuncAttributeMaxDynamicSharedMemorySize, SM_TOT);
    cudaFuncSetAttribute(mma_gemm40_kernel,
                         cudaFuncAttributeMaxDynamicSharedMemorySize, SM4_TOT);

    static cudaStream_t s2 = nullptr;
    static cudaEvent_t evA = nullptr, evB = nullptr, evG1 = nullptr;
    static cudaEvent_t evG2c0 = nullptr, evG2c1 = nullptr, ev40c1 = nullptr;
    if (s2 == nullptr) {
        cudaStreamCreateWithFlags(&s2, cudaStreamNonBlocking);
        cudaEventCreateWithFlags(&evA, cudaEventDisableTiming);
        cudaEventCreateWithFlags(&evB, cudaEventDisableTiming);
        cudaEventCreateWithFlags(&evG1, cudaEventDisableTiming);
        cudaEventCreateWithFlags(&evG2c0, cudaEventDisableTiming);
        cudaEventCreateWithFlags(&evG2c1, cudaEventDisableTiming);
        cudaEventCreateWithFlags(&ev40c1, cudaEventDisableTiming);
    }

    const int T = 256;
    int csrThreads = (E0 >> 2) + n;
    int csrBlocks  = (csrThreads + T - 1) / T;
    int scanBlocks = (n + 1023) / 1024;
    int nodeBlocks = (n + T - 1) / T;
    int mmaBlocks  = (n + 127) / 128;
    int warpNodeBlocks = (n * 32 + T - 1) / T;

    int half = ((n / 2 + 127) / 128) * 128;   // 25088
    int c1   = n - half;
    int gB0  = half / 128;
    int gB1  = (c1 + 127) / 128;
    int aB0  = (half * 32 + T - 1) / T;
    int aB1  = (c1 * 32 + T - 1) / T;

    // ---- fork: CSR build on s2, concurrent with layer-1 GEMM ----
    cudaEventRecord(evA, 0);
    cudaStreamWaitEvent(s2, evA, 0);

    cudaMemsetAsync(p_deg, 0, n * sizeof(int), s2);
    hist_kernel<<<csrBlocks, T, 0, s2>>>(ei, E0, n, p_deg, p_rank);
    scan1_kernel<<<scanBlocks, 1024, 0, s2>>>(p_deg, p_incl, p_bsum, n);
    scan3_kernel<<<nodeBlocks, T, 0, s2>>>(p_incl, p_bsum, p_rowptr, n, scanBlocks);
    scatter_kernel<<<csrBlocks, T, 0, s2>>>(ei, E0, n, p_rowptr, p_rank, p_csrsrc);

    // ---------------- layer 1 GEMM (full, on s0) ----------------
    mma_gemm128_kernel<true><<<mmaBlocks, T, SM_TOT>>>(
        x, nullptr, W1, a_src1, a_dst1, p_hph, p_als, p_ald, 0, n);
    cudaEventRecord(evG1, 0);
    cudaEventRecord(evB, s2);

    // ---------------- pipelined layers: chunk0 on s0, chunk1 on s2 ----------------
    cudaStreamWaitEvent(0, evB, 0);
    cudaStreamWaitEvent(s2, evG1, 0);
    fusedagg128_kernel<<<aB0, T>>>(p_rowptr, p_csrsrc, p_hph, p_als, p_ald,
                                   b1, bn1_g, bn1_b, bn1_m, bn1_v,
                                   p_feat, 0, half);
    fusedagg128_kernel<<<aB1, T, 0, s2>>>(p_rowptr, p_csrsrc, p_hph, p_als, p_ald,
                                          b1, bn1_g, bn1_b, bn1_m, bn1_v,
                                          p_feat, half, c1);
    mma_gemm128_kernel<false><<<gB0, T, SM_TOT>>>(
        nullptr, p_feat, W2, a_src2, a_dst2, p_hph, p_als, p_ald, 0, n);
    cudaEventRecord(evG2c0, 0);
    mma_gemm128_kernel<false><<<gB1, T, SM_TOT, s2>>>(
        nullptr, p_feat, W2, a_src2, a_dst2, p_hph, p_als, p_ald, half, n);
    cudaEventRecord(evG2c1, s2);

    cudaStreamWaitEvent(0, evG2c1, 0);
    cudaStreamWaitEvent(s2, evG2c0, 0);
    fusedagg128_kernel<<<aB0, T>>>(p_rowptr, p_csrsrc, p_hph, p_als, p_ald,
                                   b2, bn2_g, bn2_b, bn2_m, bn2_v,
                                   p_feat, 0, half);
    fusedagg128_kernel<<<aB1, T, 0, s2>>>(p_rowptr, p_csrsrc, p_hph, p_als, p_ald,
                                          b2, bn2_g, bn2_b, bn2_m, bn2_v,
                                          p_feat, half, c1);
    mma_gemm40_kernel<<<gB0, T, SM4_TOT>>>(p_feat, W3, a_src3, a_dst3,
                                           p_hp3, p_als, p_ald, 0, n);
    mma_gemm40_kernel<<<gB1, T, SM4_TOT, s2>>>(p_feat, W3, a_src3, a_dst3,
                                               p_hp3, p_als, p_ald, half, n);
    cudaEventRecord(ev40c1, s2);

    cudaStreamWaitEvent(0, ev40c1, 0);
    fusedagg40_kernel<<<warpNodeBlocks, T>>>(p_rowptr, p_csrsrc, p_hp3, p_als, p_ald,
                                             b3, out, n);
}